// round 6
// baseline (speedup 1.0000x reference)
#include <cuda_runtime.h>
#include <cuda_bf16.h>
#include <cuda_fp16.h>
#include <cstdint>

using bf16 = __nv_bfloat16;

#define DEVI __device__ __forceinline__

constexpr int Bc = 4;      // batch
constexpr int Nt = 2048;   // tokens
constexpr int Dc = 1024;   // model dim
constexpr int Fc = 4096;   // ffn dim
constexpr int Mrows = Bc * Nt;   // 8192

constexpr int BM = 128, BN = 128, BK = 32;
constexpr int SA_ST   = BK + 8;    // 40 (16-bit elems)
constexpr int SBKN_ST = BN + 8;    // 136
constexpr int NTHREADS = 256;

// int8 GEMM: 64 int8 per K-tile, 80-byte padded rows
constexpr int QBK   = 64;
constexpr int QST   = 80;

// ---------------- scratch ----------------------------------------------------
__device__ __align__(16) bf16        g_T[(size_t)Nt * Nt];
__device__ __align__(16) bf16        g_xb[(size_t)Bc * Nt * Dc];
__device__ __align__(16) float       g_y1[(size_t)Bc * Nt * Dc];
__device__ __align__(16) float       g_x1[(size_t)Bc * Nt * Dc];
__device__ __align__(16) signed char g_x1q[(size_t)Bc * Nt * Dc];
__device__              float        g_sx[(size_t)Mrows];
__device__ __align__(16) signed char g_W1q[(size_t)Fc * Dc];
__device__              float        g_sw1[(size_t)Fc];
__device__ __align__(16) __half      g_W2h[(size_t)Dc * Fc];
__device__ __align__(16) __half      g_H[(size_t)Bc * Nt * Fc];
__device__ __align__(16) float       g_y2[(size_t)Bc * Nt * Dc];

// ---------------- PTX helpers -------------------------------------------------
DEVI uint32_t smem_u32(const void* p) {
    return static_cast<uint32_t>(__cvta_generic_to_shared(p));
}
DEVI void cp_async16(uint32_t sdst, const void* gsrc) {
    asm volatile("cp.async.cg.shared.global [%0], [%1], 16;\n" :: "r"(sdst), "l"(gsrc));
}
DEVI void cp_commit() { asm volatile("cp.async.commit_group;\n"); }
template <int N> DEVI void cp_wait() {
    asm volatile("cp.async.wait_group %0;\n" :: "n"(N));
}
DEVI void ldmx4(uint32_t& r0, uint32_t& r1, uint32_t& r2, uint32_t& r3, uint32_t a) {
    asm volatile("ldmatrix.sync.aligned.m8n8.x4.shared.b16 {%0,%1,%2,%3}, [%4];\n"
                 : "=r"(r0), "=r"(r1), "=r"(r2), "=r"(r3) : "r"(a));
}
DEVI void ldmx4t(uint32_t& r0, uint32_t& r1, uint32_t& r2, uint32_t& r3, uint32_t a) {
    asm volatile("ldmatrix.sync.aligned.m8n8.x4.trans.shared.b16 {%0,%1,%2,%3}, [%4];\n"
                 : "=r"(r0), "=r"(r1), "=r"(r2), "=r"(r3) : "r"(a));
}
DEVI void mma16816_bf(float c[4], const uint32_t a[4], const uint32_t b[2]) {
    asm volatile(
        "mma.sync.aligned.m16n8k16.row.col.f32.bf16.bf16.f32 "
        "{%0,%1,%2,%3}, {%4,%5,%6,%7}, {%8,%9}, {%0,%1,%2,%3};\n"
        : "+f"(c[0]), "+f"(c[1]), "+f"(c[2]), "+f"(c[3])
        : "r"(a[0]), "r"(a[1]), "r"(a[2]), "r"(a[3]), "r"(b[0]), "r"(b[1]));
}
DEVI void mma16816_hf32(float c[4], const uint32_t a[4], const uint32_t b[2]) {
    asm volatile(
        "mma.sync.aligned.m16n8k16.row.col.f32.f16.f16.f32 "
        "{%0,%1,%2,%3}, {%4,%5,%6,%7}, {%8,%9}, {%0,%1,%2,%3};\n"
        : "+f"(c[0]), "+f"(c[1]), "+f"(c[2]), "+f"(c[3])
        : "r"(a[0]), "r"(a[1]), "r"(a[2]), "r"(a[3]), "r"(b[0]), "r"(b[1]));
}
DEVI void mma16832_s8(int c[4], const uint32_t a[4], const uint32_t b[2]) {
    asm volatile(
        "mma.sync.aligned.m16n8k32.row.col.s32.s8.s8.s32 "
        "{%0,%1,%2,%3}, {%4,%5,%6,%7}, {%8,%9}, {%0,%1,%2,%3};\n"
        : "+r"(c[0]), "+r"(c[1]), "+r"(c[2]), "+r"(c[3])
        : "r"(a[0]), "r"(a[1]), "r"(a[2]), "r"(a[3]), "r"(b[0]), "r"(b[1]));
}
DEVI float gelu_exact(float v) {
    return 0.5f * v * (1.0f + erff(v * 0.70710678118654752f));
}
DEVI int q8(float v, float inv) {
    int q = __float2int_rn(v * inv);
    return max(-127, min(127, q));
}

// ---------------- prep kernels ----------------------------------------------
__global__ void cvt_x_kernel(const float* __restrict__ src, int n4)
{
    int i = blockIdx.x * blockDim.x + threadIdx.x;
    if (i < n4) {
        float4 v = reinterpret_cast<const float4*>(src)[i];
        __nv_bfloat162* d2 = reinterpret_cast<__nv_bfloat162*>(g_xb) + 2 * (size_t)i;
        d2[0] = __floats2bfloat162_rn(v.x, v.y);
        d2[1] = __floats2bfloat162_rn(v.z, v.w);
    }
}

__global__ void cvt_w2_kernel(const float* __restrict__ src, int n4)
{
    int i = blockIdx.x * blockDim.x + threadIdx.x;
    if (i < n4) {
        float4 v = reinterpret_cast<const float4*>(src)[i];
        __half2* d2 = reinterpret_cast<__half2*>(g_W2h) + 2 * (size_t)i;
        d2[0] = __floats2half2_rn(v.x, v.y);
        d2[1] = __floats2half2_rn(v.z, v.w);
    }
}

// per-output-row int8 quantization of W1 [Fc, Dc]
__global__ void __launch_bounds__(256) quantW1_kernel(const float* __restrict__ W1)
{
    const size_t f = blockIdx.x;
    const int t = threadIdx.x;
    float4 v = reinterpret_cast<const float4*>(W1 + f * Dc)[t];
    float m = fmaxf(fmaxf(fabsf(v.x), fabsf(v.y)), fmaxf(fabsf(v.z), fabsf(v.w)));
#pragma unroll
    for (int o = 16; o > 0; o >>= 1)
        m = fmaxf(m, __shfl_xor_sync(0xffffffffu, m, o));
    __shared__ float red[8];
    if ((t & 31) == 0) red[t >> 5] = m;
    __syncthreads();
    m = 0.0f;
#pragma unroll
    for (int i = 0; i < 8; i++) m = fmaxf(m, red[i]);
    m = fmaxf(m, 1e-20f);
    const float inv = 127.0f / m;
    const int q0 = q8(v.x, inv), q1 = q8(v.y, inv), q2 = q8(v.z, inv), q3 = q8(v.w, inv);
    const uint32_t p = (uint32_t)(q0 & 0xff) | ((uint32_t)(q1 & 0xff) << 8)
                     | ((uint32_t)(q2 & 0xff) << 16) | ((uint32_t)(q3 & 0xff) << 24);
    reinterpret_cast<uint32_t*>(g_W1q + f * Dc)[t] = p;
    if (t == 0) g_sw1[f] = m * (1.0f / 127.0f);
}

__global__ void buildT_kernel(const float* __restrict__ w)
{
    int i = blockIdx.x * blockDim.x + threadIdx.x;
    int n = i >> 11;
    int m = i & (Nt - 1);
    float v = (m <= n) ? w[n - m] : 0.0f;
    g_T[i] = __float2bfloat16(v);
}

// ---------------- conv GEMM (bf16, f32 acc, triangular K skip) ----------------
__global__ void __launch_bounds__(NTHREADS, 2) conv_gemm_kernel(
    const float* __restrict__ x, const float* __restrict__ scale)
{
    constexpr int K = Nt;
    constexpr int Nc = Dc;

    const bf16* __restrict__ A  = g_T;
    const bf16* __restrict__ Bp = g_xb + (size_t)blockIdx.z * Nt * Dc;

    __shared__ __align__(16) bf16 sA[2][BM * SA_ST];
    __shared__ __align__(16) bf16 sB[2][BK * SBKN_ST];

    const int tid  = threadIdx.x;
    const int bm0  = blockIdx.y * BM;
    const int bn0  = blockIdx.x * BN;
    const int wid  = tid >> 5;
    const int lane = tid & 31;
    const int wm   = (wid & 3) * 32;
    const int wn   = (wid >> 2) * 64;
    const int kmax = (bm0 + BM) / BK;

    float acc[2][8][4];
#pragma unroll
    for (int i = 0; i < 2; i++)
#pragma unroll
        for (int j = 0; j < 8; j++)
#pragma unroll
            for (int q = 0; q < 4; q++) acc[i][j][q] = 0.0f;

    auto load_tiles = [&](int s, int kt) {
        const bf16* Ag = A + (size_t)bm0 * K + (size_t)kt * BK;
#pragma unroll
        for (int i = 0; i < 2; i++) {
            int ch  = tid + i * NTHREADS;
            int row = ch >> 2;
            int col = (ch & 3) * 8;
            cp_async16(smem_u32(&sA[s][row * SA_ST + col]), Ag + (size_t)row * K + col);
        }
        const bf16* Bg = Bp + (size_t)(kt * BK) * Nc + bn0;
#pragma unroll
        for (int i = 0; i < 2; i++) {
            int ch  = tid + i * NTHREADS;
            int row = ch >> 4;
            int col = (ch & 15) * 8;
            cp_async16(smem_u32(&sB[s][row * SBKN_ST + col]), Bg + (size_t)row * Nc + col);
        }
        cp_commit();
    };

    load_tiles(0, 0);

    for (int kt = 0; kt < kmax; kt++) {
        const int s = kt & 1;
        if (kt + 1 < kmax) { load_tiles(s ^ 1, kt + 1); cp_wait<1>(); }
        else               { cp_wait<0>(); }
        __syncthreads();

#pragma unroll
        for (int kk = 0; kk < BK; kk += 16) {
            uint32_t a[2][4];
#pragma unroll
            for (int i = 0; i < 2; i++) {
                const bf16* p = &sA[s][(wm + i * 16 + (lane & 15)) * SA_ST
                                       + kk + (lane >> 4) * 8];
                ldmx4(a[i][0], a[i][1], a[i][2], a[i][3], smem_u32(p));
            }
            uint32_t b[8][2];
#pragma unroll
            for (int j = 0; j < 8; j += 2) {
                uint32_t r0, r1, r2, r3;
                const bf16* p = &sB[s][(kk + (lane & 15)) * SBKN_ST
                                       + wn + j * 8 + (lane >> 4) * 8];
                ldmx4t(r0, r1, r2, r3, smem_u32(p));
                b[j][0] = r0; b[j][1] = r1; b[j + 1][0] = r2; b[j + 1][1] = r3;
            }
#pragma unroll
            for (int i = 0; i < 2; i++)
#pragma unroll
                for (int j = 0; j < 8; j++)
                    mma16816_bf(acc[i][j], a[i], b[j]);
        }
        __syncthreads();
    }

    const int rbase = bm0 + wm + (lane >> 2);
    const int cbase = bn0 + wn + (lane & 3) * 2;
#pragma unroll
    for (int i = 0; i < 2; i++)
#pragma unroll
        for (int j = 0; j < 8; j++)
#pragma unroll
            for (int h = 0; h < 2; h++) {
                const int r = rbase + i * 16 + h * 8;
                const int c = cbase + j * 8;
                const size_t o = (size_t)blockIdx.z * (Nt * Dc) + (size_t)r * Dc + c;
                const float sc = scale[r];
                float2 ov = make_float2(x[o] + acc[i][j][h * 2] * sc,
                                        x[o + 1] + acc[i][j][h * 2 + 1] * sc);
                *reinterpret_cast<float2*>(g_y1 + o) = ov;
            }
}

// ---------------- MLP GEMM 1 (int8 IMMA, s32 acc) ------------------------------
// A=g_x1q [8192,1024] s8, B=g_W1q [4096,1024] s8 -> g_H = half(gelu(acc*sx*sw + b1))
__global__ void __launch_bounds__(NTHREADS, 2) mlp1_int8_kernel(
    const float* __restrict__ bias)
{
    constexpr int K  = Dc;
    constexpr int KT = K / QBK;   // 16

    __shared__ __align__(16) signed char sA[2][BM * QST];   // 20 KB
    __shared__ __align__(16) signed char sB[2][BN * QST];   // 20 KB

    const int tid  = threadIdx.x;
    const int wid  = tid >> 5;
    const int lane = tid & 31;
    const int bm0  = blockIdx.y * BM;
    const int bn0  = blockIdx.x * BN;
    const int wm   = (wid & 3) * 32;
    const int wn   = (wid >> 2) * 64;

    int acc[2][8][4];
#pragma unroll
    for (int i = 0; i < 2; i++)
#pragma unroll
        for (int j = 0; j < 8; j++)
#pragma unroll
            for (int q = 0; q < 4; q++) acc[i][j][q] = 0;

    auto load_tiles = [&](int s, int kt) {
        const signed char* Ag = g_x1q + (size_t)bm0 * K + (size_t)kt * QBK;
#pragma unroll
        for (int i = 0; i < 2; i++) {            // 512 chunks: 128 rows x 4x16B
            int ch  = tid + i * NTHREADS;
            int row = ch >> 2;
            int col = (ch & 3) * 16;
            cp_async16(smem_u32(&sA[s][row * QST + col]), Ag + (size_t)row * K + col);
        }
        const signed char* Bg = g_W1q + (size_t)bn0 * K + (size_t)kt * QBK;
#pragma unroll
        for (int i = 0; i < 2; i++) {
            int ch  = tid + i * NTHREADS;
            int row = ch >> 2;
            int col = (ch & 3) * 16;
            cp_async16(smem_u32(&sB[s][row * QST + col]), Bg + (size_t)row * K + col);
        }
        cp_commit();
    };

    load_tiles(0, 0);

    for (int kt = 0; kt < KT; kt++) {
        const int s = kt & 1;
        if (kt + 1 < KT) { load_tiles(s ^ 1, kt + 1); cp_wait<1>(); }
        else             { cp_wait<0>(); }
        __syncthreads();

#pragma unroll
        for (int kq = 0; kq < 2; kq++) {          // two k32 steps per 64B tile
            uint32_t a[2][4];
#pragma unroll
            for (int i = 0; i < 2; i++) {
                const signed char* p = &sA[s][(wm + i * 16 + (lane & 15)) * QST
                                              + kq * 32 + (lane >> 4) * 16];
                ldmx4(a[i][0], a[i][1], a[i][2], a[i][3], smem_u32(p));
            }
            uint32_t b[8][2];
#pragma unroll
            for (int j = 0; j < 8; j += 2) {
                uint32_t r0, r1, r2, r3;
                int rr = wn + j * 8 + ((lane >> 4) << 3) + (lane & 7);
                int cc = kq * 32 + ((lane >> 3) & 1) * 16;
                const signed char* p = &sB[s][rr * QST + cc];
                ldmx4(r0, r1, r2, r3, smem_u32(p));
                b[j][0] = r0; b[j][1] = r1; b[j + 1][0] = r2; b[j + 1][1] = r3;
            }
#pragma unroll
            for (int i = 0; i < 2; i++)
#pragma unroll
                for (int j = 0; j < 8; j++)
                    mma16832_s8(acc[i][j], a[i], b[j]);
        }
        __syncthreads();
    }

    // epilogue: dequant, bias, gelu, store half
    const int rbase = bm0 + wm + (lane >> 2);
    const int cbase = bn0 + wn + (lane & 3) * 2;
#pragma unroll
    for (int i = 0; i < 2; i++) {
#pragma unroll
        for (int h = 0; h < 2; h++) {
            const int r = rbase + i * 16 + h * 8;
            const float sx = g_sx[r];
#pragma unroll
            for (int j = 0; j < 8; j++) {
                const int c = cbase + j * 8;
                const float s0 = sx * g_sw1[c];
                const float s1 = sx * g_sw1[c + 1];
                float v0 = (float)acc[i][j][h * 2 + 0] * s0 + bias[c];
                float v1 = (float)acc[i][j][h * 2 + 1] * s1 + bias[c + 1];
                __half2 ov = __floats2half2_rn(gelu_exact(v0), gelu_exact(v1));
                *reinterpret_cast<__half2*>(g_H + (size_t)r * Fc + c) = ov;
            }
        }
    }
}

// ---------------- MLP GEMM 2 (f16 inputs, f32 accumulation) --------------------
__global__ void __launch_bounds__(NTHREADS, 2) mlp2_gemm_kernel(
    const float* __restrict__ bias, const float* __restrict__ scl)
{
    constexpr int K  = Fc;
    constexpr int KT = K / BK;

    const __half* __restrict__ A = g_H;
    const __half* __restrict__ B = g_W2h;

    __shared__ __align__(16) __half sA[2][BM * SA_ST];
    __shared__ __align__(16) __half sB[2][BN * SA_ST];

    const int tid  = threadIdx.x;
    const int wid  = tid >> 5;
    const int lane = tid & 31;
    const int bm0  = blockIdx.y * BM;
    const int bn0  = blockIdx.x * BN;
    const int wm   = (wid & 3) * 32;
    const int wn   = (wid >> 2) * 64;

    float acc[2][8][4];
#pragma unroll
    for (int i = 0; i < 2; i++)
#pragma unroll
        for (int j = 0; j < 8; j++)
#pragma unroll
            for (int q = 0; q < 4; q++) acc[i][j][q] = 0.0f;

    auto load_tiles = [&](int s, int kt) {
        const __half* Ag = A + (size_t)bm0 * K + (size_t)kt * BK;
#pragma unroll
        for (int i = 0; i < 2; i++) {
            int ch  = tid + i * NTHREADS;
            int row = ch >> 2;
            int col = (ch & 3) * 8;
            cp_async16(smem_u32(&sA[s][row * SA_ST + col]), Ag + (size_t)row * K + col);
        }
        const __half* Bg = B + (size_t)bn0 * K + (size_t)kt * BK;
#pragma unroll
        for (int i = 0; i < 2; i++) {
            int ch  = tid + i * NTHREADS;
            int row = ch >> 2;
            int col = (ch & 3) * 8;
            cp_async16(smem_u32(&sB[s][row * SA_ST + col]), Bg + (size_t)row * K + col);
        }
        cp_commit();
    };

    load_tiles(0, 0);

    for (int kt = 0; kt < KT; kt++) {
        const int s = kt & 1;
        if (kt + 1 < KT) { load_tiles(s ^ 1, kt + 1); cp_wait<1>(); }
        else             { cp_wait<0>(); }
        __syncthreads();

#pragma unroll
        for (int kk = 0; kk < BK; kk += 16) {
            uint32_t a[2][4];
#pragma unroll
            for (int i = 0; i < 2; i++) {
                const __half* p = &sA[s][(wm + i * 16 + (lane & 15)) * SA_ST
                                         + kk + (lane >> 4) * 8];
                ldmx4(a[i][0], a[i][1], a[i][2], a[i][3], smem_u32(p));
            }
            uint32_t b[8][2];
#pragma unroll
            for (int j = 0; j < 8; j += 2) {
                uint32_t r0, r1, r2, r3;
                int rr = wn + j * 8 + ((lane >> 4) << 3) + (lane & 7);
                int cc = kk + ((lane >> 3) & 1) * 8;
                const __half* p = &sB[s][rr * SA_ST + cc];
                ldmx4(r0, r1, r2, r3, smem_u32(p));
                b[j][0] = r0; b[j][1] = r1; b[j + 1][0] = r2; b[j + 1][1] = r3;
            }
#pragma unroll
            for (int i = 0; i < 2; i++)
#pragma unroll
                for (int j = 0; j < 8; j++)
                    mma16816_hf32(acc[i][j], a[i], b[j]);
        }
        __syncthreads();
    }

    float sscal = scl[0];
    const int rbase = bm0 + wm + (lane >> 2);
    const int cbase = bn0 + wn + (lane & 3) * 2;
#pragma unroll
    for (int i = 0; i < 2; i++)
#pragma unroll
        for (int j = 0; j < 8; j++)
#pragma unroll
            for (int h = 0; h < 2; h++) {
                const int r = rbase + i * 16 + h * 8;
                const int c = cbase + j * 8;
                const size_t o = (size_t)r * Dc + c;
                float2 xv = *reinterpret_cast<const float2*>(g_x1 + o);
                float2 ov = make_float2(
                    xv.x + sscal * (acc[i][j][h * 2]     + bias[c]),
                    xv.y + sscal * (acc[i][j][h * 2 + 1] + bias[c + 1]));
                *reinterpret_cast<float2*>(g_y2 + o) = ov;
            }
}

// ---------------- LayerNorm ---------------------------------------------------
// WHICH=1: LN(g_y1) -> g_x1 (f32) + fused per-row int8 quant -> g_x1q, g_sx
// WHICH=2: LN(g_y2) -> out
template <int WHICH>
__global__ void __launch_bounds__(256) ln_kernel(
    const float* __restrict__ lw, const float* __restrict__ lb,
    float* __restrict__ outp)
{
    const float* __restrict__ in = (WHICH == 1) ? g_y1 : g_y2;
    const size_t row = blockIdx.x;
    const int t = threadIdx.x;

    float4 v = reinterpret_cast<const float4*>(in + row * Dc)[t];
    float s = v.x + v.y + v.z + v.w;
    float q = v.x * v.x + v.y * v.y + v.z * v.z + v.w * v.w;
#pragma unroll
    for (int o = 16; o > 0; o >>= 1) {
        s += __shfl_xor_sync(0xffffffffu, s, o);
        q += __shfl_xor_sync(0xffffffffu, q, o);
    }
    __shared__ float red[16];
    __shared__ float redm[8];
    if ((t & 31) == 0) { red[t >> 5] = s; red[8 + (t >> 5)] = q; }
    __syncthreads();
    s = 0.0f; q = 0.0f;
#pragma unroll
    for (int i = 0; i < 8; i++) { s += red[i]; q += red[8 + i]; }

    const float mu  = s * (1.0f / Dc);
    const float inv = rsqrtf(q * (1.0f / Dc) - mu * mu + 1e-5f);
    const int c = t * 4;
    const float o0 = (v.x - mu) * inv * lw[c + 0] + lb[c + 0];
    const float o1 = (v.y - mu) * inv * lw[c + 1] + lb[c + 1];
    const float o2 = (v.z - mu) * inv * lw[c + 2] + lb[c + 2];
    const float o3 = (v.w - mu) * inv * lw[c + 3] + lb[c + 3];

    if constexpr (WHICH == 1) {
        reinterpret_cast<float4*>(g_x1 + row * Dc)[t] = make_float4(o0, o1, o2, o3);
        // fused per-row int8 quantization
        float m = fmaxf(fmaxf(fabsf(o0), fabsf(o1)), fmaxf(fabsf(o2), fabsf(o3)));
#pragma unroll
        for (int o = 16; o > 0; o >>= 1)
            m = fmaxf(m, __shfl_xor_sync(0xffffffffu, m, o));
        if ((t & 31) == 0) redm[t >> 5] = m;
        __syncthreads();
        m = 0.0f;
#pragma unroll
        for (int i = 0; i < 8; i++) m = fmaxf(m, redm[i]);
        m = fmaxf(m, 1e-20f);
        const float qinv = 127.0f / m;
        const int q0 = q8(o0, qinv), q1 = q8(o1, qinv),
                  q2 = q8(o2, qinv), q3 = q8(o3, qinv);
        const uint32_t p = (uint32_t)(q0 & 0xff) | ((uint32_t)(q1 & 0xff) << 8)
                         | ((uint32_t)(q2 & 0xff) << 16) | ((uint32_t)(q3 & 0xff) << 24);
        reinterpret_cast<uint32_t*>(g_x1q + row * Dc)[t] = p;
        if (t == 0) g_sx[row] = m * (1.0f / 127.0f);
    } else {
        reinterpret_cast<float4*>(outp + row * Dc)[t] = make_float4(o0, o1, o2, o3);
    }
}

// ---------------- launch --------------------------------------------------------
extern "C" void kernel_launch(void* const* d_in, const int* in_sizes, int n_in,
                              void* d_out, int out_size)
{
    const float* x       = (const float*)d_in[0];
    const float* weights = (const float*)d_in[1];
    const float* scale   = (const float*)d_in[2];
    const float* ln1w    = (const float*)d_in[3];
    const float* ln1b    = (const float*)d_in[4];
    const float* W1      = (const float*)d_in[5];
    const float* b1      = (const float*)d_in[6];
    const float* W2      = (const float*)d_in[7];
    const float* b2      = (const float*)d_in[8];
    const float* scalar  = (const float*)d_in[9];
    const float* ln2w    = (const float*)d_in[10];
    const float* ln2b    = (const float*)d_in[11];
    float* out = (float*)d_out;

    // prep
    {
        int n4x = Bc * Nt * Dc / 4;
        cvt_x_kernel<<<(n4x + 255) / 256, 256>>>(x, n4x);
        int n4w = Fc * Dc / 4;
        cvt_w2_kernel<<<(n4w + 255) / 256, 256>>>(W2, n4w);
        quantW1_kernel<<<Fc, 256>>>(W1);
        buildT_kernel<<<(Nt * Nt) / 256, 256>>>(weights);
    }

    // conv (triangular Toeplitz GEMM) + residual scale-add
    conv_gemm_kernel<<<dim3(Dc / BN, Nt / BM, Bc), NTHREADS>>>(x, scale);
    // LN1 (+ fused int8 quantization)
    ln_kernel<1><<<Bc * Nt, 256>>>(ln1w, ln1b, nullptr);
    // MLP up + GELU (int8 IMMA)
    mlp1_int8_kernel<<<dim3(Fc / BN, Mrows / BM), NTHREADS>>>(b1);
    // MLP down + scalar residual (f16/f32)
    mlp2_gemm_kernel<<<dim3(Dc / BN, Mrows / BM), NTHREADS>>>(b2, scalar);
    // LN2 -> output
    ln_kernel<2><<<Bc * Nt, 256>>>(ln2w, ln2b, out);
}

// round 7
// speedup vs baseline: 1.5022x; 1.5022x over previous
#include <cuda_runtime.h>
#include <cuda_bf16.h>
#include <cuda_fp16.h>
#include <cstdint>

using bf16 = __nv_bfloat16;

#define DEVI __device__ __forceinline__

constexpr int Bc = 4;      // batch
constexpr int Nt = 2048;   // tokens
constexpr int Dc = 1024;   // model dim
constexpr int Fc = 4096;   // ffn dim
constexpr int Mrows = Bc * Nt;   // 8192
constexpr int KSPLIT = 4;        // GEMM2 split-K factor

constexpr int BM = 128, BN = 128, BK = 32;
constexpr int SA_ST   = BK + 8;    // 40
constexpr int SBKN_ST = BN + 8;    // 136
constexpr int NTHREADS = 256;

// ---------------- scratch ----------------------------------------------------
__device__ __align__(16) bf16   g_T[(size_t)Nt * Nt];
__device__ __align__(16) bf16   g_xb[(size_t)Bc * Nt * Dc];
__device__ __align__(16) float  g_y1[(size_t)Bc * Nt * Dc];
__device__ __align__(16) float  g_x1[(size_t)Bc * Nt * Dc];
__device__ __align__(16) __half g_x1h[(size_t)Bc * Nt * Dc];
__device__ __align__(16) __half g_W1h[(size_t)Fc * Dc];
__device__ __align__(16) __half g_W2h[(size_t)Dc * Fc];
__device__ __align__(16) __half g_H[(size_t)Bc * Nt * Fc];
__device__ __align__(16) float  g_p2[(size_t)KSPLIT * Mrows * Dc];  // split-K partials

// ---------------- PTX helpers -------------------------------------------------
DEVI uint32_t smem_u32(const void* p) {
    return static_cast<uint32_t>(__cvta_generic_to_shared(p));
}
DEVI void cp_async16(uint32_t sdst, const void* gsrc) {
    asm volatile("cp.async.cg.shared.global [%0], [%1], 16;\n" :: "r"(sdst), "l"(gsrc));
}
DEVI void cp_commit() { asm volatile("cp.async.commit_group;\n"); }
template <int N> DEVI void cp_wait() {
    asm volatile("cp.async.wait_group %0;\n" :: "n"(N));
}
DEVI void ldmx4(uint32_t& r0, uint32_t& r1, uint32_t& r2, uint32_t& r3, uint32_t a) {
    asm volatile("ldmatrix.sync.aligned.m8n8.x4.shared.b16 {%0,%1,%2,%3}, [%4];\n"
                 : "=r"(r0), "=r"(r1), "=r"(r2), "=r"(r3) : "r"(a));
}
DEVI void ldmx4t(uint32_t& r0, uint32_t& r1, uint32_t& r2, uint32_t& r3, uint32_t a) {
    asm volatile("ldmatrix.sync.aligned.m8n8.x4.trans.shared.b16 {%0,%1,%2,%3}, [%4];\n"
                 : "=r"(r0), "=r"(r1), "=r"(r2), "=r"(r3) : "r"(a));
}
DEVI void mma16816_bf(float c[4], const uint32_t a[4], const uint32_t b[2]) {
    asm volatile(
        "mma.sync.aligned.m16n8k16.row.col.f32.bf16.bf16.f32 "
        "{%0,%1,%2,%3}, {%4,%5,%6,%7}, {%8,%9}, {%0,%1,%2,%3};\n"
        : "+f"(c[0]), "+f"(c[1]), "+f"(c[2]), "+f"(c[3])
        : "r"(a[0]), "r"(a[1]), "r"(a[2]), "r"(a[3]), "r"(b[0]), "r"(b[1]));
}
DEVI void mma16816_hf32(float c[4], const uint32_t a[4], const uint32_t b[2]) {
    asm volatile(
        "mma.sync.aligned.m16n8k16.row.col.f32.f16.f16.f32 "
        "{%0,%1,%2,%3}, {%4,%5,%6,%7}, {%8,%9}, {%0,%1,%2,%3};\n"
        : "+f"(c[0]), "+f"(c[1]), "+f"(c[2]), "+f"(c[3])
        : "r"(a[0]), "r"(a[1]), "r"(a[2]), "r"(a[3]), "r"(b[0]), "r"(b[1]));
}
DEVI void mma16816_hf16(uint32_t c[2], const uint32_t a[4], const uint32_t b[2]) {
    asm volatile(
        "mma.sync.aligned.m16n8k16.row.col.f16.f16.f16.f16 "
        "{%0,%1}, {%2,%3,%4,%5}, {%6,%7}, {%0,%1};\n"
        : "+r"(c[0]), "+r"(c[1])
        : "r"(a[0]), "r"(a[1]), "r"(a[2]), "r"(a[3]), "r"(b[0]), "r"(b[1]));
}
DEVI float gelu_exact(float v) {
    return 0.5f * v * (1.0f + erff(v * 0.70710678118654752f));
}

// ---------------- prep kernels ----------------------------------------------
__global__ void cvt_x_kernel(const float* __restrict__ src, int n4)
{
    int i = blockIdx.x * blockDim.x + threadIdx.x;
    if (i < n4) {
        float4 v = reinterpret_cast<const float4*>(src)[i];
        __nv_bfloat162* d2 = reinterpret_cast<__nv_bfloat162*>(g_xb) + 2 * (size_t)i;
        d2[0] = __floats2bfloat162_rn(v.x, v.y);
        d2[1] = __floats2bfloat162_rn(v.z, v.w);
    }
}

template <int W>
__global__ void cvt_w_kernel(const float* __restrict__ src, int n4)
{
    __half* dst = (W == 1) ? g_W1h : g_W2h;
    int i = blockIdx.x * blockDim.x + threadIdx.x;
    if (i < n4) {
        float4 v = reinterpret_cast<const float4*>(src)[i];
        __half2* d2 = reinterpret_cast<__half2*>(dst) + 2 * (size_t)i;
        d2[0] = __floats2half2_rn(v.x, v.y);
        d2[1] = __floats2half2_rn(v.z, v.w);
    }
}

__global__ void buildT_kernel(const float* __restrict__ w)
{
    int i = blockIdx.x * blockDim.x + threadIdx.x;
    int n = i >> 11;
    int m = i & (Nt - 1);
    float v = (m <= n) ? w[n - m] : 0.0f;
    g_T[i] = __float2bfloat16(v);
}

// ---------------- conv GEMM (bf16, f32 acc, triangular skip, longest-first) ---
__global__ void __launch_bounds__(NTHREADS, 2) conv_gemm_kernel(
    const float* __restrict__ x, const float* __restrict__ scale)
{
    constexpr int K = Nt;
    constexpr int Nc = Dc;

    const bf16* __restrict__ A  = g_T;
    const bf16* __restrict__ Bp = g_xb + (size_t)blockIdx.z * Nt * Dc;

    __shared__ __align__(16) bf16 sA[2][BM * SA_ST];
    __shared__ __align__(16) bf16 sB[2][BK * SBKN_ST];

    const int tid  = threadIdx.x;
    // longest rows first: reverse y so kmax=16 CTAs schedule in wave 1
    const int ybm  = (int)gridDim.y - 1 - (int)blockIdx.y;
    const int bm0  = ybm * BM;
    const int bn0  = blockIdx.x * BN;
    const int wid  = tid >> 5;
    const int lane = tid & 31;
    const int wm   = (wid & 3) * 32;
    const int wn   = (wid >> 2) * 64;
    const int kmax = (bm0 + BM) / BK;

    float acc[2][8][4];
#pragma unroll
    for (int i = 0; i < 2; i++)
#pragma unroll
        for (int j = 0; j < 8; j++)
#pragma unroll
            for (int q = 0; q < 4; q++) acc[i][j][q] = 0.0f;

    auto load_tiles = [&](int s, int kt) {
        const bf16* Ag = A + (size_t)bm0 * K + (size_t)kt * BK;
#pragma unroll
        for (int i = 0; i < 2; i++) {
            int ch  = tid + i * NTHREADS;
            int row = ch >> 2;
            int col = (ch & 3) * 8;
            cp_async16(smem_u32(&sA[s][row * SA_ST + col]), Ag + (size_t)row * K + col);
        }
        const bf16* Bg = Bp + (size_t)(kt * BK) * Nc + bn0;
#pragma unroll
        for (int i = 0; i < 2; i++) {
            int ch  = tid + i * NTHREADS;
            int row = ch >> 4;
            int col = (ch & 15) * 8;
            cp_async16(smem_u32(&sB[s][row * SBKN_ST + col]), Bg + (size_t)row * Nc + col);
        }
        cp_commit();
    };

    load_tiles(0, 0);

    for (int kt = 0; kt < kmax; kt++) {
        const int s = kt & 1;
        if (kt + 1 < kmax) { load_tiles(s ^ 1, kt + 1); cp_wait<1>(); }
        else               { cp_wait<0>(); }
        __syncthreads();

#pragma unroll
        for (int kk = 0; kk < BK; kk += 16) {
            uint32_t a[2][4];
#pragma unroll
            for (int i = 0; i < 2; i++) {
                const bf16* p = &sA[s][(wm + i * 16 + (lane & 15)) * SA_ST
                                       + kk + (lane >> 4) * 8];
                ldmx4(a[i][0], a[i][1], a[i][2], a[i][3], smem_u32(p));
            }
            uint32_t b[8][2];
#pragma unroll
            for (int j = 0; j < 8; j += 2) {
                uint32_t r0, r1, r2, r3;
                const bf16* p = &sB[s][(kk + (lane & 15)) * SBKN_ST
                                       + wn + j * 8 + (lane >> 4) * 8];
                ldmx4t(r0, r1, r2, r3, smem_u32(p));
                b[j][0] = r0; b[j][1] = r1; b[j + 1][0] = r2; b[j + 1][1] = r3;
            }
#pragma unroll
            for (int i = 0; i < 2; i++)
#pragma unroll
                for (int j = 0; j < 8; j++)
                    mma16816_bf(acc[i][j], a[i], b[j]);
        }
        __syncthreads();
    }

    const int rbase = bm0 + wm + (lane >> 2);
    const int cbase = bn0 + wn + (lane & 3) * 2;
#pragma unroll
    for (int i = 0; i < 2; i++)
#pragma unroll
        for (int j = 0; j < 8; j++)
#pragma unroll
            for (int h = 0; h < 2; h++) {
                const int r = rbase + i * 16 + h * 8;
                const int c = cbase + j * 8;
                const size_t o = (size_t)blockIdx.z * (Nt * Dc) + (size_t)r * Dc + c;
                const float sc = scale[r];
                float2 ov = make_float2(x[o] + acc[i][j][h * 2] * sc,
                                        x[o + 1] + acc[i][j][h * 2 + 1] * sc);
                *reinterpret_cast<float2*>(g_y1 + o) = ov;
            }
}

// ---------------- MLP GEMM 1 (f16 inputs, f16 accumulation) --------------------
__global__ void __launch_bounds__(NTHREADS, 2) mlp1_gemm_kernel(
    const float* __restrict__ bias)
{
    constexpr int K  = Dc;
    constexpr int KT = K / BK;

    const __half* __restrict__ A = g_x1h;
    const __half* __restrict__ B = g_W1h;

    __shared__ __align__(16) __half sA[2][BM * SA_ST];
    __shared__ __align__(16) __half sB[2][BN * SA_ST];

    const int tid  = threadIdx.x;
    const int wid  = tid >> 5;
    const int lane = tid & 31;
    const int bm0  = blockIdx.y * BM;
    const int bn0  = blockIdx.x * BN;
    const int wm   = (wid & 3) * 32;
    const int wn   = (wid >> 2) * 64;

    uint32_t acc[2][8][2];
#pragma unroll
    for (int i = 0; i < 2; i++)
#pragma unroll
        for (int j = 0; j < 8; j++) { acc[i][j][0] = 0u; acc[i][j][1] = 0u; }

    auto load_tiles = [&](int s, int kt) {
        const __half* Ag = A + (size_t)bm0 * K + (size_t)kt * BK;
#pragma unroll
        for (int i = 0; i < 2; i++) {
            int ch  = tid + i * NTHREADS;
            int row = ch >> 2;
            int col = (ch & 3) * 8;
            cp_async16(smem_u32(&sA[s][row * SA_ST + col]), Ag + (size_t)row * K + col);
        }
        const __half* Bg = B + (size_t)bn0 * K + (size_t)kt * BK;
#pragma unroll
        for (int i = 0; i < 2; i++) {
            int ch  = tid + i * NTHREADS;
            int row = ch >> 2;
            int col = (ch & 3) * 8;
            cp_async16(smem_u32(&sB[s][row * SA_ST + col]), Bg + (size_t)row * K + col);
        }
        cp_commit();
    };

    load_tiles(0, 0);

    for (int kt = 0; kt < KT; kt++) {
        const int s = kt & 1;
        if (kt + 1 < KT) { load_tiles(s ^ 1, kt + 1); cp_wait<1>(); }
        else             { cp_wait<0>(); }
        __syncthreads();

#pragma unroll
        for (int kk = 0; kk < BK; kk += 16) {
            uint32_t a[2][4];
#pragma unroll
            for (int i = 0; i < 2; i++) {
                const __half* p = &sA[s][(wm + i * 16 + (lane & 15)) * SA_ST
                                         + kk + (lane >> 4) * 8];
                ldmx4(a[i][0], a[i][1], a[i][2], a[i][3], smem_u32(p));
            }
            uint32_t b[8][2];
#pragma unroll
            for (int j = 0; j < 8; j += 2) {
                uint32_t r0, r1, r2, r3;
                int rr = wn + j * 8 + ((lane >> 4) << 3) + (lane & 7);
                int cc = kk + ((lane >> 3) & 1) * 8;
                const __half* p = &sB[s][rr * SA_ST + cc];
                ldmx4(r0, r1, r2, r3, smem_u32(p));
                b[j][0] = r0; b[j][1] = r1; b[j + 1][0] = r2; b[j + 1][1] = r3;
            }
#pragma unroll
            for (int i = 0; i < 2; i++)
#pragma unroll
                for (int j = 0; j < 8; j++)
                    mma16816_hf16(acc[i][j], a[i], b[j]);
        }
        __syncthreads();
    }

    const int rbase = bm0 + wm + (lane >> 2);
    const int cbase = bn0 + wn + (lane & 3) * 2;
#pragma unroll
    for (int i = 0; i < 2; i++) {
#pragma unroll
        for (int j = 0; j < 8; j++) {
#pragma unroll
            for (int h = 0; h < 2; h++) {
                const int r = rbase + i * 16 + h * 8;
                const int c = cbase + j * 8;
                __half2 hv = *reinterpret_cast<const __half2*>(&acc[i][j][h]);
                float v0 = __half2float(__low2half(hv))  + bias[c];
                float v1 = __half2float(__high2half(hv)) + bias[c + 1];
                __half2 ov = __floats2half2_rn(gelu_exact(v0), gelu_exact(v1));
                *reinterpret_cast<__half2*>(g_H + (size_t)r * Fc + c) = ov;
            }
        }
    }
}

// ---------------- MLP GEMM 2 (f16 in, f32 acc, split-K=4) ----------------------
// slice z computes partial sum over K segment [z*1024, (z+1)*1024) -> g_p2 slice z
__global__ void __launch_bounds__(NTHREADS, 2) mlp2_gemm_kernel()
{
    constexpr int K  = Fc;
    constexpr int KS = Fc / KSPLIT;   // 1024
    constexpr int KT = KS / BK;       // 32

    const int kofs = blockIdx.z * KS;
    const __half* __restrict__ A = g_H + kofs;
    const __half* __restrict__ B = g_W2h + kofs;

    __shared__ __align__(16) __half sA[2][BM * SA_ST];
    __shared__ __align__(16) __half sB[2][BN * SA_ST];

    const int tid  = threadIdx.x;
    const int wid  = tid >> 5;
    const int lane = tid & 31;
    const int bm0  = blockIdx.y * BM;
    const int bn0  = blockIdx.x * BN;
    const int wm   = (wid & 3) * 32;
    const int wn   = (wid >> 2) * 64;

    float acc[2][8][4];
#pragma unroll
    for (int i = 0; i < 2; i++)
#pragma unroll
        for (int j = 0; j < 8; j++)
#pragma unroll
            for (int q = 0; q < 4; q++) acc[i][j][q] = 0.0f;

    auto load_tiles = [&](int s, int kt) {
        const __half* Ag = A + (size_t)bm0 * K + (size_t)kt * BK;
#pragma unroll
        for (int i = 0; i < 2; i++) {
            int ch  = tid + i * NTHREADS;
            int row = ch >> 2;
            int col = (ch & 3) * 8;
            cp_async16(smem_u32(&sA[s][row * SA_ST + col]), Ag + (size_t)row * K + col);
        }
        const __half* Bg = B + (size_t)bn0 * K + (size_t)kt * BK;
#pragma unroll
        for (int i = 0; i < 2; i++) {
            int ch  = tid + i * NTHREADS;
            int row = ch >> 2;
            int col = (ch & 3) * 8;
            cp_async16(smem_u32(&sB[s][row * SA_ST + col]), Bg + (size_t)row * K + col);
        }
        cp_commit();
    };

    load_tiles(0, 0);

    for (int kt = 0; kt < KT; kt++) {
        const int s = kt & 1;
        if (kt + 1 < KT) { load_tiles(s ^ 1, kt + 1); cp_wait<1>(); }
        else             { cp_wait<0>(); }
        __syncthreads();

#pragma unroll
        for (int kk = 0; kk < BK; kk += 16) {
            uint32_t a[2][4];
#pragma unroll
            for (int i = 0; i < 2; i++) {
                const __half* p = &sA[s][(wm + i * 16 + (lane & 15)) * SA_ST
                                         + kk + (lane >> 4) * 8];
                ldmx4(a[i][0], a[i][1], a[i][2], a[i][3], smem_u32(p));
            }
            uint32_t b[8][2];
#pragma unroll
            for (int j = 0; j < 8; j += 2) {
                uint32_t r0, r1, r2, r3;
                int rr = wn + j * 8 + ((lane >> 4) << 3) + (lane & 7);
                int cc = kk + ((lane >> 3) & 1) * 8;
                const __half* p = &sB[s][rr * SA_ST + cc];
                ldmx4(r0, r1, r2, r3, smem_u32(p));
                b[j][0] = r0; b[j][1] = r1; b[j + 1][0] = r2; b[j + 1][1] = r3;
            }
#pragma unroll
            for (int i = 0; i < 2; i++)
#pragma unroll
                for (int j = 0; j < 8; j++)
                    mma16816_hf32(acc[i][j], a[i], b[j]);
        }
        __syncthreads();
    }

    float* __restrict__ P = g_p2 + (size_t)blockIdx.z * Mrows * Dc;
    const int rbase = bm0 + wm + (lane >> 2);
    const int cbase = bn0 + wn + (lane & 3) * 2;
#pragma unroll
    for (int i = 0; i < 2; i++)
#pragma unroll
        for (int j = 0; j < 8; j++)
#pragma unroll
            for (int h = 0; h < 2; h++) {
                const int r = rbase + i * 16 + h * 8;
                const int c = cbase + j * 8;
                const size_t o = (size_t)r * Dc + c;
                float2 ov = make_float2(acc[i][j][h * 2], acc[i][j][h * 2 + 1]);
                *reinterpret_cast<float2*>(P + o) = ov;
            }
}

// ---------------- LayerNorm 1 (y1 -> x1 f32 + x1 f16) --------------------------
__global__ void __launch_bounds__(256) ln1_kernel(
    const float* __restrict__ lw, const float* __restrict__ lb)
{
    const size_t row = blockIdx.x;
    const int t = threadIdx.x;

    float4 v = reinterpret_cast<const float4*>(g_y1 + row * Dc)[t];
    float s = v.x + v.y + v.z + v.w;
    float q = v.x * v.x + v.y * v.y + v.z * v.z + v.w * v.w;
#pragma unroll
    for (int o = 16; o > 0; o >>= 1) {
        s += __shfl_xor_sync(0xffffffffu, s, o);
        q += __shfl_xor_sync(0xffffffffu, q, o);
    }
    __shared__ float red[16];
    if ((t & 31) == 0) { red[t >> 5] = s; red[8 + (t >> 5)] = q; }
    __syncthreads();
    s = 0.0f; q = 0.0f;
#pragma unroll
    for (int i = 0; i < 8; i++) { s += red[i]; q += red[8 + i]; }

    const float mu  = s * (1.0f / Dc);
    const float inv = rsqrtf(q * (1.0f / Dc) - mu * mu + 1e-5f);
    const int c = t * 4;
    const float o0 = (v.x - mu) * inv * lw[c + 0] + lb[c + 0];
    const float o1 = (v.y - mu) * inv * lw[c + 1] + lb[c + 1];
    const float o2 = (v.z - mu) * inv * lw[c + 2] + lb[c + 2];
    const float o3 = (v.w - mu) * inv * lw[c + 3] + lb[c + 3];

    reinterpret_cast<float4*>(g_x1 + row * Dc)[t] = make_float4(o0, o1, o2, o3);
    __half2* ph = reinterpret_cast<__half2*>(g_x1h + row * Dc) + t * 2;
    ph[0] = __floats2half2_rn(o0, o1);
    ph[1] = __floats2half2_rn(o2, o3);
}

// ---------------- LayerNorm 2 (4-way split-K reduce + residual + LN -> out) ----
__global__ void __launch_bounds__(256) ln2_kernel(
    const float* __restrict__ b2, const float* __restrict__ scl,
    const float* __restrict__ lw, const float* __restrict__ lb,
    float* __restrict__ outp)
{
    const size_t row = blockIdx.x;
    const int t = threadIdx.x;
    const float sscal = scl[0];

    float4 xv = reinterpret_cast<const float4*>(g_x1 + row * Dc)[t];
    float4 bv = reinterpret_cast<const float4*>(b2)[t];
    float4 p  = make_float4(0.f, 0.f, 0.f, 0.f);
#pragma unroll
    for (int z = 0; z < KSPLIT; z++) {
        float4 pz = reinterpret_cast<const float4*>(
            g_p2 + (size_t)z * Mrows * Dc + row * Dc)[t];
        p.x += pz.x; p.y += pz.y; p.z += pz.z; p.w += pz.w;
    }
    float4 v;
    v.x = xv.x + sscal * (p.x + bv.x);
    v.y = xv.y + sscal * (p.y + bv.y);
    v.z = xv.z + sscal * (p.z + bv.z);
    v.w = xv.w + sscal * (p.w + bv.w);

    float s = v.x + v.y + v.z + v.w;
    float q = v.x * v.x + v.y * v.y + v.z * v.z + v.w * v.w;
#pragma unroll
    for (int o = 16; o > 0; o >>= 1) {
        s += __shfl_xor_sync(0xffffffffu, s, o);
        q += __shfl_xor_sync(0xffffffffu, q, o);
    }
    __shared__ float red[16];
    if ((t & 31) == 0) { red[t >> 5] = s; red[8 + (t >> 5)] = q; }
    __syncthreads();
    s = 0.0f; q = 0.0f;
#pragma unroll
    for (int i = 0; i < 8; i++) { s += red[i]; q += red[8 + i]; }

    const float mu  = s * (1.0f / Dc);
    const float inv = rsqrtf(q * (1.0f / Dc) - mu * mu + 1e-5f);
    const int c = t * 4;
    float4 ov;
    ov.x = (v.x - mu) * inv * lw[c + 0] + lb[c + 0];
    ov.y = (v.y - mu) * inv * lw[c + 1] + lb[c + 1];
    ov.z = (v.z - mu) * inv * lw[c + 2] + lb[c + 2];
    ov.w = (v.w - mu) * inv * lw[c + 3] + lb[c + 3];
    reinterpret_cast<float4*>(outp + row * Dc)[t] = ov;
}

// ---------------- launch --------------------------------------------------------
extern "C" void kernel_launch(void* const* d_in, const int* in_sizes, int n_in,
                              void* d_out, int out_size)
{
    const float* x       = (const float*)d_in[0];
    const float* weights = (const float*)d_in[1];
    const float* scale   = (const float*)d_in[2];
    const float* ln1w    = (const float*)d_in[3];
    const float* ln1b    = (const float*)d_in[4];
    const float* W1      = (const float*)d_in[5];
    const float* b1      = (const float*)d_in[6];
    const float* W2      = (const float*)d_in[7];
    const float* b2      = (const float*)d_in[8];
    const float* scalar  = (const float*)d_in[9];
    const float* ln2w    = (const float*)d_in[10];
    const float* ln2b    = (const float*)d_in[11];
    float* out = (float*)d_out;

    // prep
    {
        int n4x = Bc * Nt * Dc / 4;
        cvt_x_kernel<<<(n4x + 255) / 256, 256>>>(x, n4x);
        int n4w = Fc * Dc / 4;
        cvt_w_kernel<1><<<(n4w + 255) / 256, 256>>>(W1, n4w);
        cvt_w_kernel<2><<<(n4w + 255) / 256, 256>>>(W2, n4w);
        buildT_kernel<<<(Nt * Nt) / 256, 256>>>(weights);
    }

    // conv (triangular Toeplitz GEMM, longest-first) + residual scale-add
    conv_gemm_kernel<<<dim3(Dc / BN, Nt / BM, Bc), NTHREADS>>>(x, scale);
    // LN1
    ln1_kernel<<<Bc * Nt, 256>>>(ln1w, ln1b);
    // MLP up + GELU (f16 accumulate)
    mlp1_gemm_kernel<<<dim3(Fc / BN, Mrows / BM), NTHREADS>>>(b1);
    // MLP down, split-K=4 partials
    mlp2_gemm_kernel<<<dim3(Dc / BN, Mrows / BM, KSPLIT), NTHREADS>>>();
    // LN2: reduce partials + bias + scalar residual + LN -> output
    ln2_kernel<<<Bc * Nt, 256>>>(b2, scalar, ln2w, ln2b, out);
}

// round 8
// speedup vs baseline: 1.5033x; 1.0008x over previous
#include <cuda_runtime.h>
#include <cuda_bf16.h>
#include <cuda_fp16.h>
#include <cstdint>

using bf16 = __nv_bfloat16;

#define DEVI __device__ __forceinline__

constexpr int Bc = 4;      // batch
constexpr int Nt = 2048;   // tokens
constexpr int Dc = 1024;   // model dim
constexpr int Fc = 4096;   // ffn dim
constexpr int Mrows = Bc * Nt;   // 8192
constexpr int KSPLIT = 4;        // GEMM2 split-K factor

constexpr int BM = 128, BN = 128, BK = 32;
constexpr int SA_ST   = BK + 8;    // 40
constexpr int SBKN_ST = BN + 8;    // 136
constexpr int NTHREADS = 256;

// ---------------- scratch ----------------------------------------------------
__device__ __align__(16) bf16   g_T[(size_t)Nt * Nt];
__device__ __align__(16) bf16   g_xb[(size_t)Bc * Nt * Dc];
__device__ __align__(16) float  g_y1[(size_t)Bc * Nt * Dc];
__device__ __align__(16) float  g_x1[(size_t)Bc * Nt * Dc];
__device__ __align__(16) __half g_x1h[(size_t)Bc * Nt * Dc];
__device__ __align__(16) __half g_W1h[(size_t)Fc * Dc];
__device__ __align__(16) __half g_W2h[(size_t)Dc * Fc];
__device__ __align__(16) __half g_H[(size_t)Bc * Nt * Fc];
__device__ __align__(16) float  g_p2[(size_t)KSPLIT * Mrows * Dc];  // split-K partials

// ---------------- PTX helpers -------------------------------------------------
DEVI uint32_t smem_u32(const void* p) {
    return static_cast<uint32_t>(__cvta_generic_to_shared(p));
}
DEVI void cp_async16(uint32_t sdst, const void* gsrc) {
    asm volatile("cp.async.cg.shared.global [%0], [%1], 16;\n" :: "r"(sdst), "l"(gsrc));
}
DEVI void cp_commit() { asm volatile("cp.async.commit_group;\n"); }
template <int N> DEVI void cp_wait() {
    asm volatile("cp.async.wait_group %0;\n" :: "n"(N));
}
DEVI void ldmx4(uint32_t& r0, uint32_t& r1, uint32_t& r2, uint32_t& r3, uint32_t a) {
    asm volatile("ldmatrix.sync.aligned.m8n8.x4.shared.b16 {%0,%1,%2,%3}, [%4];\n"
                 : "=r"(r0), "=r"(r1), "=r"(r2), "=r"(r3) : "r"(a));
}
DEVI void ldmx4t(uint32_t& r0, uint32_t& r1, uint32_t& r2, uint32_t& r3, uint32_t a) {
    asm volatile("ldmatrix.sync.aligned.m8n8.x4.trans.shared.b16 {%0,%1,%2,%3}, [%4];\n"
                 : "=r"(r0), "=r"(r1), "=r"(r2), "=r"(r3) : "r"(a));
}
DEVI void mma16816_bf(float c[4], const uint32_t a[4], const uint32_t b[2]) {
    asm volatile(
        "mma.sync.aligned.m16n8k16.row.col.f32.bf16.bf16.f32 "
        "{%0,%1,%2,%3}, {%4,%5,%6,%7}, {%8,%9}, {%0,%1,%2,%3};\n"
        : "+f"(c[0]), "+f"(c[1]), "+f"(c[2]), "+f"(c[3])
        : "r"(a[0]), "r"(a[1]), "r"(a[2]), "r"(a[3]), "r"(b[0]), "r"(b[1]));
}
DEVI void mma16816_hf32(float c[4], const uint32_t a[4], const uint32_t b[2]) {
    asm volatile(
        "mma.sync.aligned.m16n8k16.row.col.f32.f16.f16.f32 "
        "{%0,%1,%2,%3}, {%4,%5,%6,%7}, {%8,%9}, {%0,%1,%2,%3};\n"
        : "+f"(c[0]), "+f"(c[1]), "+f"(c[2]), "+f"(c[3])
        : "r"(a[0]), "r"(a[1]), "r"(a[2]), "r"(a[3]), "r"(b[0]), "r"(b[1]));
}
DEVI void mma16816_hf16(uint32_t c[2], const uint32_t a[4], const uint32_t b[2]) {
    asm volatile(
        "mma.sync.aligned.m16n8k16.row.col.f16.f16.f16.f16 "
        "{%0,%1}, {%2,%3,%4,%5}, {%6,%7}, {%0,%1};\n"
        : "+r"(c[0]), "+r"(c[1])
        : "r"(a[0]), "r"(a[1]), "r"(a[2]), "r"(a[3]), "r"(b[0]), "r"(b[1]));
}
DEVI float gelu_exact(float v) {
    return 0.5f * v * (1.0f + erff(v * 0.70710678118654752f));
}

// ---------------- prep kernels ----------------------------------------------
__global__ void cvt_x_kernel(const float* __restrict__ src, int n4)
{
    int i = blockIdx.x * blockDim.x + threadIdx.x;
    if (i < n4) {
        float4 v = reinterpret_cast<const float4*>(src)[i];
        __nv_bfloat162* d2 = reinterpret_cast<__nv_bfloat162*>(g_xb) + 2 * (size_t)i;
        d2[0] = __floats2bfloat162_rn(v.x, v.y);
        d2[1] = __floats2bfloat162_rn(v.z, v.w);
    }
}

// fused W1+W2 fp32 -> fp16 conversion (one launch on the side stream)
__global__ void cvt_w_both_kernel(const float* __restrict__ W1,
                                  const float* __restrict__ W2, int n4each)
{
    int i = blockIdx.x * blockDim.x + threadIdx.x;
    const float* src;
    __half* dst;
    int idx;
    if (i < n4each)        { src = W1; dst = g_W1h; idx = i; }
    else if (i < 2 * n4each) { src = W2; dst = g_W2h; idx = i - n4each; }
    else return;
    float4 v = reinterpret_cast<const float4*>(src)[idx];
    __half2* d2 = reinterpret_cast<__half2*>(dst) + 2 * (size_t)idx;
    d2[0] = __floats2half2_rn(v.x, v.y);
    d2[1] = __floats2half2_rn(v.z, v.w);
}

__global__ void buildT_kernel(const float* __restrict__ w)
{
    int i = blockIdx.x * blockDim.x + threadIdx.x;
    int n = i >> 11;
    int m = i & (Nt - 1);
    float v = (m <= n) ? w[n - m] : 0.0f;
    g_T[i] = __float2bfloat16(v);
}

// ---------------- conv GEMM (bf16, f32 acc, triangular skip, longest-first) ---
__global__ void __launch_bounds__(NTHREADS, 2) conv_gemm_kernel(
    const float* __restrict__ x, const float* __restrict__ scale)
{
    constexpr int K = Nt;
    constexpr int Nc = Dc;

    const bf16* __restrict__ A  = g_T;
    const bf16* __restrict__ Bp = g_xb + (size_t)blockIdx.z * Nt * Dc;

    __shared__ __align__(16) bf16 sA[2][BM * SA_ST];
    __shared__ __align__(16) bf16 sB[2][BK * SBKN_ST];

    const int tid  = threadIdx.x;
    const int ybm  = (int)gridDim.y - 1 - (int)blockIdx.y;   // longest-first
    const int bm0  = ybm * BM;
    const int bn0  = blockIdx.x * BN;
    const int wid  = tid >> 5;
    const int lane = tid & 31;
    const int wm   = (wid & 3) * 32;
    const int wn   = (wid >> 2) * 64;
    const int kmax = (bm0 + BM) / BK;

    float acc[2][8][4];
#pragma unroll
    for (int i = 0; i < 2; i++)
#pragma unroll
        for (int j = 0; j < 8; j++)
#pragma unroll
            for (int q = 0; q < 4; q++) acc[i][j][q] = 0.0f;

    auto load_tiles = [&](int s, int kt) {
        const bf16* Ag = A + (size_t)bm0 * K + (size_t)kt * BK;
#pragma unroll
        for (int i = 0; i < 2; i++) {
            int ch  = tid + i * NTHREADS;
            int row = ch >> 2;
            int col = (ch & 3) * 8;
            cp_async16(smem_u32(&sA[s][row * SA_ST + col]), Ag + (size_t)row * K + col);
        }
        const bf16* Bg = Bp + (size_t)(kt * BK) * Nc + bn0;
#pragma unroll
        for (int i = 0; i < 2; i++) {
            int ch  = tid + i * NTHREADS;
            int row = ch >> 4;
            int col = (ch & 15) * 8;
            cp_async16(smem_u32(&sB[s][row * SBKN_ST + col]), Bg + (size_t)row * Nc + col);
        }
        cp_commit();
    };

    load_tiles(0, 0);

    for (int kt = 0; kt < kmax; kt++) {
        const int s = kt & 1;
        if (kt + 1 < kmax) { load_tiles(s ^ 1, kt + 1); cp_wait<1>(); }
        else               { cp_wait<0>(); }
        __syncthreads();

#pragma unroll
        for (int kk = 0; kk < BK; kk += 16) {
            uint32_t a[2][4];
#pragma unroll
            for (int i = 0; i < 2; i++) {
                const bf16* p = &sA[s][(wm + i * 16 + (lane & 15)) * SA_ST
                                       + kk + (lane >> 4) * 8];
                ldmx4(a[i][0], a[i][1], a[i][2], a[i][3], smem_u32(p));
            }
            uint32_t b[8][2];
#pragma unroll
            for (int j = 0; j < 8; j += 2) {
                uint32_t r0, r1, r2, r3;
                const bf16* p = &sB[s][(kk + (lane & 15)) * SBKN_ST
                                       + wn + j * 8 + (lane >> 4) * 8];
                ldmx4t(r0, r1, r2, r3, smem_u32(p));
                b[j][0] = r0; b[j][1] = r1; b[j + 1][0] = r2; b[j + 1][1] = r3;
            }
#pragma unroll
            for (int i = 0; i < 2; i++)
#pragma unroll
                for (int j = 0; j < 8; j++)
                    mma16816_bf(acc[i][j], a[i], b[j]);
        }
        __syncthreads();
    }

    const int rbase = bm0 + wm + (lane >> 2);
    const int cbase = bn0 + wn + (lane & 3) * 2;
#pragma unroll
    for (int i = 0; i < 2; i++)
#pragma unroll
        for (int j = 0; j < 8; j++)
#pragma unroll
            for (int h = 0; h < 2; h++) {
                const int r = rbase + i * 16 + h * 8;
                const int c = cbase + j * 8;
                const size_t o = (size_t)blockIdx.z * (Nt * Dc) + (size_t)r * Dc + c;
                const float sc = scale[r];
                float2 ov = make_float2(x[o] + acc[i][j][h * 2] * sc,
                                        x[o + 1] + acc[i][j][h * 2 + 1] * sc);
                *reinterpret_cast<float2*>(g_y1 + o) = ov;
            }
}

// ---------------- MLP GEMM 1 (f16 inputs, f16 accumulation) --------------------
__global__ void __launch_bounds__(NTHREADS, 2) mlp1_gemm_kernel(
    const float* __restrict__ bias)
{
    constexpr int K  = Dc;
    constexpr int KT = K / BK;

    const __half* __restrict__ A = g_x1h;
    const __half* __restrict__ B = g_W1h;

    __shared__ __align__(16) __half sA[2][BM * SA_ST];
    __shared__ __align__(16) __half sB[2][BN * SA_ST];

    const int tid  = threadIdx.x;
    const int wid  = tid >> 5;
    const int lane = tid & 31;
    const int bm0  = blockIdx.y * BM;
    const int bn0  = blockIdx.x * BN;
    const int wm   = (wid & 3) * 32;
    const int wn   = (wid >> 2) * 64;

    uint32_t acc[2][8][2];
#pragma unroll
    for (int i = 0; i < 2; i++)
#pragma unroll
        for (int j = 0; j < 8; j++) { acc[i][j][0] = 0u; acc[i][j][1] = 0u; }

    auto load_tiles = [&](int s, int kt) {
        const __half* Ag = A + (size_t)bm0 * K + (size_t)kt * BK;
#pragma unroll
        for (int i = 0; i < 2; i++) {
            int ch  = tid + i * NTHREADS;
            int row = ch >> 2;
            int col = (ch & 3) * 8;
            cp_async16(smem_u32(&sA[s][row * SA_ST + col]), Ag + (size_t)row * K + col);
        }
        const __half* Bg = B + (size_t)bn0 * K + (size_t)kt * BK;
#pragma unroll
        for (int i = 0; i < 2; i++) {
            int ch  = tid + i * NTHREADS;
            int row = ch >> 2;
            int col = (ch & 3) * 8;
            cp_async16(smem_u32(&sB[s][row * SA_ST + col]), Bg + (size_t)row * K + col);
        }
        cp_commit();
    };

    load_tiles(0, 0);

    for (int kt = 0; kt < KT; kt++) {
        const int s = kt & 1;
        if (kt + 1 < KT) { load_tiles(s ^ 1, kt + 1); cp_wait<1>(); }
        else             { cp_wait<0>(); }
        __syncthreads();

#pragma unroll
        for (int kk = 0; kk < BK; kk += 16) {
            uint32_t a[2][4];
#pragma unroll
            for (int i = 0; i < 2; i++) {
                const __half* p = &sA[s][(wm + i * 16 + (lane & 15)) * SA_ST
                                         + kk + (lane >> 4) * 8];
                ldmx4(a[i][0], a[i][1], a[i][2], a[i][3], smem_u32(p));
            }
            uint32_t b[8][2];
#pragma unroll
            for (int j = 0; j < 8; j += 2) {
                uint32_t r0, r1, r2, r3;
                int rr = wn + j * 8 + ((lane >> 4) << 3) + (lane & 7);
                int cc = kk + ((lane >> 3) & 1) * 8;
                const __half* p = &sB[s][rr * SA_ST + cc];
                ldmx4(r0, r1, r2, r3, smem_u32(p));
                b[j][0] = r0; b[j][1] = r1; b[j + 1][0] = r2; b[j + 1][1] = r3;
            }
#pragma unroll
            for (int i = 0; i < 2; i++)
#pragma unroll
                for (int j = 0; j < 8; j++)
                    mma16816_hf16(acc[i][j], a[i], b[j]);
        }
        __syncthreads();
    }

    const int rbase = bm0 + wm + (lane >> 2);
    const int cbase = bn0 + wn + (lane & 3) * 2;
#pragma unroll
    for (int i = 0; i < 2; i++) {
#pragma unroll
        for (int j = 0; j < 8; j++) {
#pragma unroll
            for (int h = 0; h < 2; h++) {
                const int r = rbase + i * 16 + h * 8;
                const int c = cbase + j * 8;
                __half2 hv = *reinterpret_cast<const __half2*>(&acc[i][j][h]);
                float v0 = __half2float(__low2half(hv))  + bias[c];
                float v1 = __half2float(__high2half(hv)) + bias[c + 1];
                __half2 ov = __floats2half2_rn(gelu_exact(v0), gelu_exact(v1));
                *reinterpret_cast<__half2*>(g_H + (size_t)r * Fc + c) = ov;
            }
        }
    }
}

// ---------------- MLP GEMM 2 (f16 in, f32 acc, split-K=4) ----------------------
__global__ void __launch_bounds__(NTHREADS, 2) mlp2_gemm_kernel()
{
    constexpr int K  = Fc;
    constexpr int KS = Fc / KSPLIT;   // 1024
    constexpr int KT = KS / BK;       // 32

    const int kofs = blockIdx.z * KS;
    const __half* __restrict__ A = g_H + kofs;
    const __half* __restrict__ B = g_W2h + kofs;

    __shared__ __align__(16) __half sA[2][BM * SA_ST];
    __shared__ __align__(16) __half sB[2][BN * SA_ST];

    const int tid  = threadIdx.x;
    const int wid  = tid >> 5;
    const int lane = tid & 31;
    const int bm0  = blockIdx.y * BM;
    const int bn0  = blockIdx.x * BN;
    const int wm   = (wid & 3) * 32;
    const int wn   = (wid >> 2) * 64;

    float acc[2][8][4];
#pragma unroll
    for (int i = 0; i < 2; i++)
#pragma unroll
        for (int j = 0; j < 8; j++)
#pragma unroll
            for (int q = 0; q < 4; q++) acc[i][j][q] = 0.0f;

    auto load_tiles = [&](int s, int kt) {
        const __half* Ag = A + (size_t)bm0 * K + (size_t)kt * BK;
#pragma unroll
        for (int i = 0; i < 2; i++) {
            int ch  = tid + i * NTHREADS;
            int row = ch >> 2;
            int col = (ch & 3) * 8;
            cp_async16(smem_u32(&sA[s][row * SA_ST + col]), Ag + (size_t)row * K + col);
        }
        const __half* Bg = B + (size_t)bn0 * K + (size_t)kt * BK;
#pragma unroll
        for (int i = 0; i < 2; i++) {
            int ch  = tid + i * NTHREADS;
            int row = ch >> 2;
            int col = (ch & 3) * 8;
            cp_async16(smem_u32(&sB[s][row * SA_ST + col]), Bg + (size_t)row * K + col);
        }
        cp_commit();
    };

    load_tiles(0, 0);

    for (int kt = 0; kt < KT; kt++) {
        const int s = kt & 1;
        if (kt + 1 < KT) { load_tiles(s ^ 1, kt + 1); cp_wait<1>(); }
        else             { cp_wait<0>(); }
        __syncthreads();

#pragma unroll
        for (int kk = 0; kk < BK; kk += 16) {
            uint32_t a[2][4];
#pragma unroll
            for (int i = 0; i < 2; i++) {
                const __half* p = &sA[s][(wm + i * 16 + (lane & 15)) * SA_ST
                                         + kk + (lane >> 4) * 8];
                ldmx4(a[i][0], a[i][1], a[i][2], a[i][3], smem_u32(p));
            }
            uint32_t b[8][2];
#pragma unroll
            for (int j = 0; j < 8; j += 2) {
                uint32_t r0, r1, r2, r3;
                int rr = wn + j * 8 + ((lane >> 4) << 3) + (lane & 7);
                int cc = kk + ((lane >> 3) & 1) * 8;
                const __half* p = &sB[s][rr * SA_ST + cc];
                ldmx4(r0, r1, r2, r3, smem_u32(p));
                b[j][0] = r0; b[j][1] = r1; b[j + 1][0] = r2; b[j + 1][1] = r3;
            }
#pragma unroll
            for (int i = 0; i < 2; i++)
#pragma unroll
                for (int j = 0; j < 8; j++)
                    mma16816_hf32(acc[i][j], a[i], b[j]);
        }
        __syncthreads();
    }

    float* __restrict__ P = g_p2 + (size_t)blockIdx.z * Mrows * Dc;
    const int rbase = bm0 + wm + (lane >> 2);
    const int cbase = bn0 + wn + (lane & 3) * 2;
#pragma unroll
    for (int i = 0; i < 2; i++)
#pragma unroll
        for (int j = 0; j < 8; j++)
#pragma unroll
            for (int h = 0; h < 2; h++) {
                const int r = rbase + i * 16 + h * 8;
                const int c = cbase + j * 8;
                const size_t o = (size_t)r * Dc + c;
                float2 ov = make_float2(acc[i][j][h * 2], acc[i][j][h * 2 + 1]);
                *reinterpret_cast<float2*>(P + o) = ov;
            }
}

// ---------------- LayerNorm 1 ---------------------------------------------------
__global__ void __launch_bounds__(256) ln1_kernel(
    const float* __restrict__ lw, const float* __restrict__ lb)
{
    const size_t row = blockIdx.x;
    const int t = threadIdx.x;

    float4 v = reinterpret_cast<const float4*>(g_y1 + row * Dc)[t];
    float s = v.x + v.y + v.z + v.w;
    float q = v.x * v.x + v.y * v.y + v.z * v.z + v.w * v.w;
#pragma unroll
    for (int o = 16; o > 0; o >>= 1) {
        s += __shfl_xor_sync(0xffffffffu, s, o);
        q += __shfl_xor_sync(0xffffffffu, q, o);
    }
    __shared__ float red[16];
    if ((t & 31) == 0) { red[t >> 5] = s; red[8 + (t >> 5)] = q; }
    __syncthreads();
    s = 0.0f; q = 0.0f;
#pragma unroll
    for (int i = 0; i < 8; i++) { s += red[i]; q += red[8 + i]; }

    const float mu  = s * (1.0f / Dc);
    const float inv = rsqrtf(q * (1.0f / Dc) - mu * mu + 1e-5f);
    const int c = t * 4;
    const float o0 = (v.x - mu) * inv * lw[c + 0] + lb[c + 0];
    const float o1 = (v.y - mu) * inv * lw[c + 1] + lb[c + 1];
    const float o2 = (v.z - mu) * inv * lw[c + 2] + lb[c + 2];
    const float o3 = (v.w - mu) * inv * lw[c + 3] + lb[c + 3];

    reinterpret_cast<float4*>(g_x1 + row * Dc)[t] = make_float4(o0, o1, o2, o3);
    __half2* ph = reinterpret_cast<__half2*>(g_x1h + row * Dc) + t * 2;
    ph[0] = __floats2half2_rn(o0, o1);
    ph[1] = __floats2half2_rn(o2, o3);
}

// ---------------- LayerNorm 2 (split-K reduce + residual + LN -> out) -----------
__global__ void __launch_bounds__(256) ln2_kernel(
    const float* __restrict__ b2, const float* __restrict__ scl,
    const float* __restrict__ lw, const float* __restrict__ lb,
    float* __restrict__ outp)
{
    const size_t row = blockIdx.x;
    const int t = threadIdx.x;
    const float sscal = scl[0];

    float4 xv = reinterpret_cast<const float4*>(g_x1 + row * Dc)[t];
    float4 bv = reinterpret_cast<const float4*>(b2)[t];
    float4 p  = make_float4(0.f, 0.f, 0.f, 0.f);
#pragma unroll
    for (int z = 0; z < KSPLIT; z++) {
        float4 pz = reinterpret_cast<const float4*>(
            g_p2 + (size_t)z * Mrows * Dc + row * Dc)[t];
        p.x += pz.x; p.y += pz.y; p.z += pz.z; p.w += pz.w;
    }
    float4 v;
    v.x = xv.x + sscal * (p.x + bv.x);
    v.y = xv.y + sscal * (p.y + bv.y);
    v.z = xv.z + sscal * (p.z + bv.z);
    v.w = xv.w + sscal * (p.w + bv.w);

    float s = v.x + v.y + v.z + v.w;
    float q = v.x * v.x + v.y * v.y + v.z * v.z + v.w * v.w;
#pragma unroll
    for (int o = 16; o > 0; o >>= 1) {
        s += __shfl_xor_sync(0xffffffffu, s, o);
        q += __shfl_xor_sync(0xffffffffu, q, o);
    }
    __shared__ float red[16];
    if ((t & 31) == 0) { red[t >> 5] = s; red[8 + (t >> 5)] = q; }
    __syncthreads();
    s = 0.0f; q = 0.0f;
#pragma unroll
    for (int i = 0; i < 8; i++) { s += red[i]; q += red[8 + i]; }

    const float mu  = s * (1.0f / Dc);
    const float inv = rsqrtf(q * (1.0f / Dc) - mu * mu + 1e-5f);
    const int c = t * 4;
    float4 ov;
    ov.x = (v.x - mu) * inv * lw[c + 0] + lb[c + 0];
    ov.y = (v.y - mu) * inv * lw[c + 1] + lb[c + 1];
    ov.z = (v.z - mu) * inv * lw[c + 2] + lb[c + 2];
    ov.w = (v.w - mu) * inv * lw[c + 3] + lb[c + 3];
    reinterpret_cast<float4*>(outp + row * Dc)[t] = ov;
}

// ---------------- launch --------------------------------------------------------
extern "C" void kernel_launch(void* const* d_in, const int* in_sizes, int n_in,
                              void* d_out, int out_size)
{
    const float* x       = (const float*)d_in[0];
    const float* weights = (const float*)d_in[1];
    const float* scale   = (const float*)d_in[2];
    const float* ln1w    = (const float*)d_in[3];
    const float* ln1b    = (const float*)d_in[4];
    const float* W1      = (const float*)d_in[5];
    const float* b1      = (const float*)d_in[6];
    const float* W2      = (const float*)d_in[7];
    const float* b2      = (const float*)d_in[8];
    const float* scalar  = (const float*)d_in[9];
    const float* ln2w    = (const float*)d_in[10];
    const float* ln2b    = (const float*)d_in[11];
    float* out = (float*)d_out;

    // side stream + events (created once, on the first non-captured call)
    static cudaStream_t s2 = nullptr;
    static cudaEvent_t evFork = nullptr, evJoin = nullptr;
    if (s2 == nullptr) {
        cudaStreamCreateWithFlags(&s2, cudaStreamNonBlocking);
        cudaEventCreateWithFlags(&evFork, cudaEventDisableTiming);
        cudaEventCreateWithFlags(&evJoin, cudaEventDisableTiming);
    }

    const int n4x = Bc * Nt * Dc / 4;
    const int n4w = Fc * Dc / 4;

    // fork: W1/W2 fp32->fp16 conversion on side stream, overlapping conv chain
    cudaEventRecord(evFork, 0);
    cudaStreamWaitEvent(s2, evFork, 0);
    cvt_w_both_kernel<<<(2 * n4w + 255) / 256, 256, 0, s2>>>(W1, W2, n4w);
    cudaEventRecord(evJoin, s2);

    // main stream: conv chain
    cvt_x_kernel<<<(n4x + 255) / 256, 256>>>(x, n4x);
    buildT_kernel<<<(Nt * Nt) / 256, 256>>>(weights);
    conv_gemm_kernel<<<dim3(Dc / BN, Nt / BM, Bc), NTHREADS>>>(x, scale);
    ln1_kernel<<<Bc * Nt, 256>>>(ln1w, ln1b);

    // join before the weight consumers
    cudaStreamWaitEvent(0, evJoin, 0);

    mlp1_gemm_kernel<<<dim3(Fc / BN, Mrows / BM), NTHREADS>>>(b1);
    mlp2_gemm_kernel<<<dim3(Dc / BN, Mrows / BM, KSPLIT), NTHREADS>>>();
    ln2_kernel<<<Bc * Nt, 256>>>(b2, scalar, ln2w, ln2b, out);
}

// round 10
// speedup vs baseline: 1.5275x; 1.0161x over previous
#include <cuda_runtime.h>
#include <cuda_bf16.h>
#include <cuda_fp16.h>
#include <cstdint>

using bf16 = __nv_bfloat16;

#define DEVI __device__ __forceinline__

constexpr int Bc = 4;      // batch
constexpr int Nt = 2048;   // tokens
constexpr int Dc = 1024;   // model dim
constexpr int Fc = 4096;   // ffn dim
constexpr int Mrows = Bc * Nt;   // 8192
constexpr int KSPLIT = 4;        // GEMM2 split-K factor

constexpr int BM = 128, BN = 128, BK = 32;
constexpr int SA_ST   = BK + 8;    // 40
constexpr int SBKN_ST = BN + 8;    // 136
constexpr int NTHREADS = 256;

// ---------------- scratch ----------------------------------------------------
__device__ __align__(16) bf16   g_T[(size_t)Nt * Nt];
__device__ __align__(16) bf16   g_xb[(size_t)Bc * Nt * Dc];
__device__ __align__(16) float  g_y1[(size_t)Bc * Nt * Dc];
__device__ __align__(16) float  g_x1[(size_t)Bc * Nt * Dc];
__device__ __align__(16) __half g_x1h[(size_t)Bc * Nt * Dc];
__device__ __align__(16) __half g_W1h[(size_t)Fc * Dc];
__device__ __align__(16) __half g_W2h[(size_t)Dc * Fc];
__device__ __align__(16) __half g_H[(size_t)Bc * Nt * Fc];
__device__ __align__(16) float  g_p2[(size_t)KSPLIT * Mrows * Dc];  // split-K partials

// ---------------- PTX helpers -------------------------------------------------
DEVI uint32_t smem_u32(const void* p) {
    return static_cast<uint32_t>(__cvta_generic_to_shared(p));
}
DEVI void cp_async16(uint32_t sdst, const void* gsrc) {
    asm volatile("cp.async.cg.shared.global [%0], [%1], 16;\n" :: "r"(sdst), "l"(gsrc));
}
DEVI void cp_commit() { asm volatile("cp.async.commit_group;\n"); }
template <int N> DEVI void cp_wait() {
    asm volatile("cp.async.wait_group %0;\n" :: "n"(N));
}
DEVI void ldmx4(uint32_t& r0, uint32_t& r1, uint32_t& r2, uint32_t& r3, uint32_t a) {
    asm volatile("ldmatrix.sync.aligned.m8n8.x4.shared.b16 {%0,%1,%2,%3}, [%4];\n"
                 : "=r"(r0), "=r"(r1), "=r"(r2), "=r"(r3) : "r"(a));
}
DEVI void ldmx4t(uint32_t& r0, uint32_t& r1, uint32_t& r2, uint32_t& r3, uint32_t a) {
    asm volatile("ldmatrix.sync.aligned.m8n8.x4.trans.shared.b16 {%0,%1,%2,%3}, [%4];\n"
                 : "=r"(r0), "=r"(r1), "=r"(r2), "=r"(r3) : "r"(a));
}
DEVI void mma16816_bf(float c[4], const uint32_t a[4], const uint32_t b[2]) {
    asm volatile(
        "mma.sync.aligned.m16n8k16.row.col.f32.bf16.bf16.f32 "
        "{%0,%1,%2,%3}, {%4,%5,%6,%7}, {%8,%9}, {%0,%1,%2,%3};\n"
        : "+f"(c[0]), "+f"(c[1]), "+f"(c[2]), "+f"(c[3])
        : "r"(a[0]), "r"(a[1]), "r"(a[2]), "r"(a[3]), "r"(b[0]), "r"(b[1]));
}
DEVI void mma16816_hf32(float c[4], const uint32_t a[4], const uint32_t b[2]) {
    asm volatile(
        "mma.sync.aligned.m16n8k16.row.col.f32.f16.f16.f32 "
        "{%0,%1,%2,%3}, {%4,%5,%6,%7}, {%8,%9}, {%0,%1,%2,%3};\n"
        : "+f"(c[0]), "+f"(c[1]), "+f"(c[2]), "+f"(c[3])
        : "r"(a[0]), "r"(a[1]), "r"(a[2]), "r"(a[3]), "r"(b[0]), "r"(b[1]));
}
DEVI void mma16816_hf16(uint32_t c[2], const uint32_t a[4], const uint32_t b[2]) {
    asm volatile(
        "mma.sync.aligned.m16n8k16.row.col.f16.f16.f16.f16 "
        "{%0,%1}, {%2,%3,%4,%5}, {%6,%7}, {%0,%1};\n"
        : "+r"(c[0]), "+r"(c[1])
        : "r"(a[0]), "r"(a[1]), "r"(a[2]), "r"(a[3]), "r"(b[0]), "r"(b[1]));
}
DEVI float gelu_exact(float v) {
    return 0.5f * v * (1.0f + erff(v * 0.70710678118654752f));
}

// ---------------- prep kernels ----------------------------------------------
__global__ void cvt_x_kernel(const float* __restrict__ src, int n4)
{
    int i = blockIdx.x * blockDim.x + threadIdx.x;
    if (i < n4) {
        float4 v = reinterpret_cast<const float4*>(src)[i];
        __nv_bfloat162* d2 = reinterpret_cast<__nv_bfloat162*>(g_xb) + 2 * (size_t)i;
        d2[0] = __floats2bfloat162_rn(v.x, v.y);
        d2[1] = __floats2bfloat162_rn(v.z, v.w);
    }
}

__global__ void cvt_w_both_kernel(const float* __restrict__ W1,
                                  const float* __restrict__ W2, int n4each)
{
    int i = blockIdx.x * blockDim.x + threadIdx.x;
    const float* src;
    __half* dst;
    int idx;
    if (i < n4each)          { src = W1; dst = g_W1h; idx = i; }
    else if (i < 2 * n4each) { src = W2; dst = g_W2h; idx = i - n4each; }
    else return;
    float4 v = reinterpret_cast<const float4*>(src)[idx];
    __half2* d2 = reinterpret_cast<__half2*>(dst) + 2 * (size_t)idx;
    d2[0] = __floats2half2_rn(v.x, v.y);
    d2[1] = __floats2half2_rn(v.z, v.w);
}

__global__ void buildT_kernel(const float* __restrict__ w)
{
    int i = blockIdx.x * blockDim.x + threadIdx.x;
    int n = i >> 11;
    int m = i & (Nt - 1);
    float v = (m <= n) ? w[n - m] : 0.0f;
    g_T[i] = __float2bfloat16(v);
}

// ---------------- conv GEMM (bf16, f32 acc, PAIR-BALANCED triangular) ----------
// CTA pair p handles row-block y = 15-p (kmax=4*(16-p)) then y = p (kmax=4*(p+1)):
// uniform 68 k-iters per CTA; grid 8x8x4 = 256 CTAs = single wave at 2 CTA/SM.
__global__ void __launch_bounds__(NTHREADS, 2) conv_gemm_kernel(
    const float* __restrict__ x, const float* __restrict__ scale)
{
    constexpr int K = Nt;
    constexpr int Nc = Dc;

    const bf16* __restrict__ A  = g_T;
    const bf16* __restrict__ Bp = g_xb + (size_t)blockIdx.z * Nt * Dc;

    __shared__ __align__(16) bf16 sA[2][BM * SA_ST];
    __shared__ __align__(16) bf16 sB[2][BK * SBKN_ST];

    const int tid  = threadIdx.x;
    const int pair = blockIdx.y;                  // 0..7
    const int bn0  = blockIdx.x * BN;
    const int wid  = tid >> 5;
    const int lane = tid & 31;
    const int wm   = (wid & 3) * 32;
    const int wn   = (wid >> 2) * 64;

#pragma unroll
    for (int half = 0; half < 2; half++) {
        const int ybm  = (half == 0) ? (15 - pair) : pair;   // long block first
        const int bm0  = ybm * BM;
        const int kmax = 4 * (ybm + 1);           // (bm0+BM)/BK

        float acc[2][8][4];
#pragma unroll
        for (int i = 0; i < 2; i++)
#pragma unroll
            for (int j = 0; j < 8; j++)
#pragma unroll
                for (int q = 0; q < 4; q++) acc[i][j][q] = 0.0f;

        auto load_tiles = [&](int s, int kt) {
            const bf16* Ag = A + (size_t)bm0 * K + (size_t)kt * BK;
#pragma unroll
            for (int i = 0; i < 2; i++) {
                int ch  = tid + i * NTHREADS;
                int row = ch >> 2;
                int col = (ch & 3) * 8;
                cp_async16(smem_u32(&sA[s][row * SA_ST + col]),
                           Ag + (size_t)row * K + col);
            }
            const bf16* Bg = Bp + (size_t)(kt * BK) * Nc + bn0;
#pragma unroll
            for (int i = 0; i < 2; i++) {
                int ch  = tid + i * NTHREADS;
                int row = ch >> 4;
                int col = (ch & 15) * 8;
                cp_async16(smem_u32(&sB[s][row * SBKN_ST + col]),
                           Bg + (size_t)row * Nc + col);
            }
            cp_commit();
        };

        load_tiles(0, 0);

        for (int kt = 0; kt < kmax; kt++) {
            const int s = kt & 1;
            if (kt + 1 < kmax) { load_tiles(s ^ 1, kt + 1); cp_wait<1>(); }
            else               { cp_wait<0>(); }
            __syncthreads();

#pragma unroll
            for (int kk = 0; kk < BK; kk += 16) {
                uint32_t a[2][4];
#pragma unroll
                for (int i = 0; i < 2; i++) {
                    const bf16* p = &sA[s][(wm + i * 16 + (lane & 15)) * SA_ST
                                           + kk + (lane >> 4) * 8];
                    ldmx4(a[i][0], a[i][1], a[i][2], a[i][3], smem_u32(p));
                }
                uint32_t b[8][2];
#pragma unroll
                for (int j = 0; j < 8; j += 2) {
                    uint32_t r0, r1, r2, r3;
                    const bf16* p = &sB[s][(kk + (lane & 15)) * SBKN_ST
                                           + wn + j * 8 + (lane >> 4) * 8];
                    ldmx4t(r0, r1, r2, r3, smem_u32(p));
                    b[j][0] = r0; b[j][1] = r1; b[j + 1][0] = r2; b[j + 1][1] = r3;
                }
#pragma unroll
                for (int i = 0; i < 2; i++)
#pragma unroll
                    for (int j = 0; j < 8; j++)
                        mma16816_bf(acc[i][j], a[i], b[j]);
            }
            __syncthreads();
        }

        const int rbase = bm0 + wm + (lane >> 2);
        const int cbase = bn0 + wn + (lane & 3) * 2;
#pragma unroll
        for (int i = 0; i < 2; i++)
#pragma unroll
            for (int j = 0; j < 8; j++)
#pragma unroll
                for (int h = 0; h < 2; h++) {
                    const int r = rbase + i * 16 + h * 8;
                    const int c = cbase + j * 8;
                    const size_t o = (size_t)blockIdx.z * (Nt * Dc)
                                   + (size_t)r * Dc + c;
                    const float sc = scale[r];
                    float2 ov = make_float2(x[o] + acc[i][j][h * 2] * sc,
                                            x[o + 1] + acc[i][j][h * 2 + 1] * sc);
                    *reinterpret_cast<float2*>(g_y1 + o) = ov;
                }
        __syncthreads();
    }
}

// ---------------- MLP GEMM 1 (f16 inputs, f16 accumulation) --------------------
__global__ void __launch_bounds__(NTHREADS, 2) mlp1_gemm_kernel(
    const float* __restrict__ bias)
{
    constexpr int K  = Dc;
    constexpr int KT = K / BK;

    const __half* __restrict__ A = g_x1h;
    const __half* __restrict__ B = g_W1h;

    __shared__ __align__(16) __half sA[2][BM * SA_ST];
    __shared__ __align__(16) __half sB[2][BN * SA_ST];

    const int tid  = threadIdx.x;
    const int wid  = tid >> 5;
    const int lane = tid & 31;
    const int bm0  = blockIdx.y * BM;
    const int bn0  = blockIdx.x * BN;
    const int wm   = (wid & 3) * 32;
    const int wn   = (wid >> 2) * 64;

    uint32_t acc[2][8][2];
#pragma unroll
    for (int i = 0; i < 2; i++)
#pragma unroll
        for (int j = 0; j < 8; j++) { acc[i][j][0] = 0u; acc[i][j][1] = 0u; }

    auto load_tiles = [&](int s, int kt) {
        const __half* Ag = A + (size_t)bm0 * K + (size_t)kt * BK;
#pragma unroll
        for (int i = 0; i < 2; i++) {
            int ch  = tid + i * NTHREADS;
            int row = ch >> 2;
            int col = (ch & 3) * 8;
            cp_async16(smem_u32(&sA[s][row * SA_ST + col]), Ag + (size_t)row * K + col);
        }
        const __half* Bg = B + (size_t)bn0 * K + (size_t)kt * BK;
#pragma unroll
        for (int i = 0; i < 2; i++) {
            int ch  = tid + i * NTHREADS;
            int row = ch >> 2;
            int col = (ch & 3) * 8;
            cp_async16(smem_u32(&sB[s][row * SA_ST + col]), Bg + (size_t)row * K + col);
        }
        cp_commit();
    };

    load_tiles(0, 0);

    for (int kt = 0; kt < KT; kt++) {
        const int s = kt & 1;
        if (kt + 1 < KT) { load_tiles(s ^ 1, kt + 1); cp_wait<1>(); }
        else             { cp_wait<0>(); }
        __syncthreads();

#pragma unroll
        for (int kk = 0; kk < BK; kk += 16) {
            uint32_t a[2][4];
#pragma unroll
            for (int i = 0; i < 2; i++) {
                const __half* p = &sA[s][(wm + i * 16 + (lane & 15)) * SA_ST
                                         + kk + (lane >> 4) * 8];
                ldmx4(a[i][0], a[i][1], a[i][2], a[i][3], smem_u32(p));
            }
            uint32_t b[8][2];
#pragma unroll
            for (int j = 0; j < 8; j += 2) {
                uint32_t r0, r1, r2, r3;
                int rr = wn + j * 8 + ((lane >> 4) << 3) + (lane & 7);
                int cc = kk + ((lane >> 3) & 1) * 8;
                const __half* p = &sB[s][rr * SA_ST + cc];
                ldmx4(r0, r1, r2, r3, smem_u32(p));
                b[j][0] = r0; b[j][1] = r1; b[j + 1][0] = r2; b[j + 1][1] = r3;
            }
#pragma unroll
            for (int i = 0; i < 2; i++)
#pragma unroll
                for (int j = 0; j < 8; j++)
                    mma16816_hf16(acc[i][j], a[i], b[j]);
        }
        __syncthreads();
    }

    const int rbase = bm0 + wm + (lane >> 2);
    const int cbase = bn0 + wn + (lane & 3) * 2;
#pragma unroll
    for (int i = 0; i < 2; i++) {
#pragma unroll
        for (int j = 0; j < 8; j++) {
#pragma unroll
            for (int h = 0; h < 2; h++) {
                const int r = rbase + i * 16 + h * 8;
                const int c = cbase + j * 8;
                __half2 hv = *reinterpret_cast<const __half2*>(&acc[i][j][h]);
                float v0 = __half2float(__low2half(hv))  + bias[c];
                float v1 = __half2float(__high2half(hv)) + bias[c + 1];
                __half2 ov = __floats2half2_rn(gelu_exact(v0), gelu_exact(v1));
                *reinterpret_cast<__half2*>(g_H + (size_t)r * Fc + c) = ov;
            }
        }
    }
}

// ---------------- MLP GEMM 2 (f16 in, f32 acc, split-K=4) ----------------------
__global__ void __launch_bounds__(NTHREADS, 2) mlp2_gemm_kernel()
{
    constexpr int K  = Fc;
    constexpr int KS = Fc / KSPLIT;   // 1024
    constexpr int KT = KS / BK;       // 32

    const int kofs = blockIdx.z * KS;
    const __half* __restrict__ A = g_H + kofs;
    const __half* __restrict__ B = g_W2h + kofs;

    __shared__ __align__(16) __half sA[2][BM * SA_ST];
    __shared__ __align__(16) __half sB[2][BN * SA_ST];

    const int tid  = threadIdx.x;
    const int wid  = tid >> 5;
    const int lane = tid & 31;
    const int bm0  = blockIdx.y * BM;
    const int bn0  = blockIdx.x * BN;
    const int wm   = (wid & 3) * 32;
    const int wn   = (wid >> 2) * 64;

    float acc[2][8][4];
#pragma unroll
    for (int i = 0; i < 2; i++)
#pragma unroll
        for (int j = 0; j < 8; j++)
#pragma unroll
            for (int q = 0; q < 4; q++) acc[i][j][q] = 0.0f;

    auto load_tiles = [&](int s, int kt) {
        const __half* Ag = A + (size_t)bm0 * K + (size_t)kt * BK;
#pragma unroll
        for (int i = 0; i < 2; i++) {
            int ch  = tid + i * NTHREADS;
            int row = ch >> 2;
            int col = (ch & 3) * 8;
            cp_async16(smem_u32(&sA[s][row * SA_ST + col]), Ag + (size_t)row * K + col);
        }
        const __half* Bg = B + (size_t)bn0 * K + (size_t)kt * BK;
#pragma unroll
        for (int i = 0; i < 2; i++) {
            int ch  = tid + i * NTHREADS;
            int row = ch >> 2;
            int col = (ch & 3) * 8;
            cp_async16(smem_u32(&sB[s][row * SA_ST + col]), Bg + (size_t)row * K + col);
        }
        cp_commit();
    };

    load_tiles(0, 0);

    for (int kt = 0; kt < KT; kt++) {
        const int s = kt & 1;
        if (kt + 1 < KT) { load_tiles(s ^ 1, kt + 1); cp_wait<1>(); }
        else             { cp_wait<0>(); }
        __syncthreads();

#pragma unroll
        for (int kk = 0; kk < BK; kk += 16) {
            uint32_t a[2][4];
#pragma unroll
            for (int i = 0; i < 2; i++) {
                const __half* p = &sA[s][(wm + i * 16 + (lane & 15)) * SA_ST
                                         + kk + (lane >> 4) * 8];
                ldmx4(a[i][0], a[i][1], a[i][2], a[i][3], smem_u32(p));
            }
            uint32_t b[8][2];
#pragma unroll
            for (int j = 0; j < 8; j += 2) {
                uint32_t r0, r1, r2, r3;
                int rr = wn + j * 8 + ((lane >> 4) << 3) + (lane & 7);
                int cc = kk + ((lane >> 3) & 1) * 8;
                const __half* p = &sB[s][rr * SA_ST + cc];
                ldmx4(r0, r1, r2, r3, smem_u32(p));
                b[j][0] = r0; b[j][1] = r1; b[j + 1][0] = r2; b[j + 1][1] = r3;
            }
#pragma unroll
            for (int i = 0; i < 2; i++)
#pragma unroll
                for (int j = 0; j < 8; j++)
                    mma16816_hf32(acc[i][j], a[i], b[j]);
        }
        __syncthreads();
    }

    float* __restrict__ P = g_p2 + (size_t)blockIdx.z * Mrows * Dc;
    const int rbase = bm0 + wm + (lane >> 2);
    const int cbase = bn0 + wn + (lane & 3) * 2;
#pragma unroll
    for (int i = 0; i < 2; i++)
#pragma unroll
        for (int j = 0; j < 8; j++)
#pragma unroll
            for (int h = 0; h < 2; h++) {
                const int r = rbase + i * 16 + h * 8;
                const int c = cbase + j * 8;
                const size_t o = (size_t)r * Dc + c;
                float2 ov = make_float2(acc[i][j][h * 2], acc[i][j][h * 2 + 1]);
                *reinterpret_cast<float2*>(P + o) = ov;
            }
}

// ---------------- LayerNorm 1 ---------------------------------------------------
__global__ void __launch_bounds__(256) ln1_kernel(
    const float* __restrict__ lw, const float* __restrict__ lb)
{
    const size_t row = blockIdx.x;
    const int t = threadIdx.x;

    float4 v = reinterpret_cast<const float4*>(g_y1 + row * Dc)[t];
    float s = v.x + v.y + v.z + v.w;
    float q = v.x * v.x + v.y * v.y + v.z * v.z + v.w * v.w;
#pragma unroll
    for (int o = 16; o > 0; o >>= 1) {
        s += __shfl_xor_sync(0xffffffffu, s, o);
        q += __shfl_xor_sync(0xffffffffu, q, o);
    }
    __shared__ float red[16];
    if ((t & 31) == 0) { red[t >> 5] = s; red[8 + (t >> 5)] = q; }
    __syncthreads();
    s = 0.0f; q = 0.0f;
#pragma unroll
    for (int i = 0; i < 8; i++) { s += red[i]; q += red[8 + i]; }

    const float mu  = s * (1.0f / Dc);
    const float inv = rsqrtf(q * (1.0f / Dc) - mu * mu + 1e-5f);
    const int c = t * 4;
    const float o0 = (v.x - mu) * inv * lw[c + 0] + lb[c + 0];
    const float o1 = (v.y - mu) * inv * lw[c + 1] + lb[c + 1];
    const float o2 = (v.z - mu) * inv * lw[c + 2] + lb[c + 2];
    const float o3 = (v.w - mu) * inv * lw[c + 3] + lb[c + 3];

    reinterpret_cast<float4*>(g_x1 + row * Dc)[t] = make_float4(o0, o1, o2, o3);
    __half2* ph = reinterpret_cast<__half2*>(g_x1h + row * Dc) + t * 2;
    ph[0] = __floats2half2_rn(o0, o1);
    ph[1] = __floats2half2_rn(o2, o3);
}

// ---------------- LayerNorm 2 (split-K reduce + residual + LN -> out) -----------
__global__ void __launch_bounds__(256) ln2_kernel(
    const float* __restrict__ b2, const float* __restrict__ scl,
    const float* __restrict__ lw, const float* __restrict__ lb,
    float* __restrict__ outp)
{
    const size_t row = blockIdx.x;
    const int t = threadIdx.x;
    const float sscal = scl[0];

    float4 xv = reinterpret_cast<const float4*>(g_x1 + row * Dc)[t];
    float4 bv = reinterpret_cast<const float4*>(b2)[t];
    float4 p  = make_float4(0.f, 0.f, 0.f, 0.f);
#pragma unroll
    for (int z = 0; z < KSPLIT; z++) {
        float4 pz = reinterpret_cast<const float4*>(
            g_p2 + (size_t)z * Mrows * Dc + row * Dc)[t];
        p.x += pz.x; p.y += pz.y; p.z += pz.z; p.w += pz.w;
    }
    float4 v;
    v.x = xv.x + sscal * (p.x + bv.x);
    v.y = xv.y + sscal * (p.y + bv.y);
    v.z = xv.z + sscal * (p.z + bv.z);
    v.w = xv.w + sscal * (p.w + bv.w);

    float s = v.x + v.y + v.z + v.w;
    float q = v.x * v.x + v.y * v.y + v.z * v.z + v.w * v.w;
#pragma unroll
    for (int o = 16; o > 0; o >>= 1) {
        s += __shfl_xor_sync(0xffffffffu, s, o);
        q += __shfl_xor_sync(0xffffffffu, q, o);
    }
    __shared__ float red[16];
    if ((t & 31) == 0) { red[t >> 5] = s; red[8 + (t >> 5)] = q; }
    __syncthreads();
    s = 0.0f; q = 0.0f;
#pragma unroll
    for (int i = 0; i < 8; i++) { s += red[i]; q += red[8 + i]; }

    const float mu  = s * (1.0f / Dc);
    const float inv = rsqrtf(q * (1.0f / Dc) - mu * mu + 1e-5f);
    const int c = t * 4;
    float4 ov;
    ov.x = (v.x - mu) * inv * lw[c + 0] + lb[c + 0];
    ov.y = (v.y - mu) * inv * lw[c + 1] + lb[c + 1];
    ov.z = (v.z - mu) * inv * lw[c + 2] + lb[c + 2];
    ov.w = (v.w - mu) * inv * lw[c + 3] + lb[c + 3];
    reinterpret_cast<float4*>(outp + row * Dc)[t] = ov;
}

// ---------------- launch --------------------------------------------------------
extern "C" void kernel_launch(void* const* d_in, const int* in_sizes, int n_in,
                              void* d_out, int out_size)
{
    const float* x       = (const float*)d_in[0];
    const float* weights = (const float*)d_in[1];
    const float* scale   = (const float*)d_in[2];
    const float* ln1w    = (const float*)d_in[3];
    const float* ln1b    = (const float*)d_in[4];
    const float* W1      = (const float*)d_in[5];
    const float* b1      = (const float*)d_in[6];
    const float* W2      = (const float*)d_in[7];
    const float* b2      = (const float*)d_in[8];
    const float* scalar  = (const float*)d_in[9];
    const float* ln2w    = (const float*)d_in[10];
    const float* ln2b    = (const float*)d_in[11];
    float* out = (float*)d_out;

    static cudaStream_t s2 = nullptr;
    static cudaEvent_t evFork = nullptr, evJoin = nullptr;
    if (s2 == nullptr) {
        cudaStreamCreateWithFlags(&s2, cudaStreamNonBlocking);
        cudaEventCreateWithFlags(&evFork, cudaEventDisableTiming);
        cudaEventCreateWithFlags(&evJoin, cudaEventDisableTiming);
    }

    const int n4x = Bc * Nt * Dc / 4;
    const int n4w = Fc * Dc / 4;

    // fork: W1/W2 fp32->fp16 conversion on side stream
    cudaEventRecord(evFork, 0);
    cudaStreamWaitEvent(s2, evFork, 0);
    cvt_w_both_kernel<<<(2 * n4w + 255) / 256, 256, 0, s2>>>(W1, W2, n4w);
    cudaEventRecord(evJoin, s2);

    // main stream: conv chain
    cvt_x_kernel<<<(n4x + 255) / 256, 256>>>(x, n4x);
    buildT_kernel<<<(Nt * Nt) / 256, 256>>>(weights);
    // pair-balanced triangular conv GEMM: grid (8, 8, 4), 68 k-iters per CTA
    conv_gemm_kernel<<<dim3(Dc / BN, 8, Bc), NTHREADS>>>(x, scale);
    ln1_kernel<<<Bc * Nt, 256>>>(ln1w, ln1b);

    cudaStreamWaitEvent(0, evJoin, 0);

    mlp1_gemm_kernel<<<dim3(Fc / BN, Mrows / BM), NTHREADS>>>(b1);
    mlp2_gemm_kernel<<<dim3(Dc / BN, Mrows / BM, KSPLIT), NTHREADS>>>();
    ln2_kernel<<<Bc * Nt, 256>>>(b2, scalar, ln2w, ln2b, out);
}